// round 3
// baseline (speedup 1.0000x reference)
#include <cuda_runtime.h>
#include <math.h>
#include <stdint.h>

// Problem constants
#define B_   4
#define S_   4096
#define D_   1024
#define F_   256
#define MR   (B_*S_)        // 16384 rows
#define CCH  64             // chunks per batch for the scan
#define LCH  (S_/CCH)       // 64 steps per chunk

// ---------------------------------------------------------------------------
// Device scratch (no allocations allowed -> __device__ globals)
// ---------------------------------------------------------------------------
__device__ float  g_xn  [MR * D_];        // LN1 output, reused as h (gelu out)
__device__ float  g_spec[MR * 2 * F_];    // spectral (GEMM1 out)
__device__ float  g_so  [MR * 2 * F_];    // spectral_out (scan out)
__device__ float  g_h2  [MR * D_];        // GEMM4 out (pre-LN2)
__device__ float2 g_carry[B_ * CCH * F_];
__device__ float2 g_cin  [B_ * CCH * F_];
__device__ double g_errsum;

// ---------------------------------------------------------------------------
// Row LayerNorm: one block (256 thr) per row of 1024 floats
// ---------------------------------------------------------------------------
__global__ void ln_rows(const float* __restrict__ x, const float* __restrict__ g,
                        const float* __restrict__ bb, float* __restrict__ out)
{
    __shared__ float sh[16];
    const int row = blockIdx.x;
    const int t   = threadIdx.x;
    const float4* xr = (const float4*)(x + (size_t)row * D_);
    float4 v = xr[t];
    float s = v.x + v.y + v.z + v.w;
    float q = v.x*v.x + v.y*v.y + v.z*v.z + v.w*v.w;
#pragma unroll
    for (int o = 16; o > 0; o >>= 1) {
        s += __shfl_down_sync(0xffffffffu, s, o);
        q += __shfl_down_sync(0xffffffffu, q, o);
    }
    if ((t & 31) == 0) { sh[t >> 5] = s; sh[8 + (t >> 5)] = q; }
    __syncthreads();
    if (t == 0) {
        float S = 0.f, Q = 0.f;
#pragma unroll
        for (int w = 0; w < 8; w++) { S += sh[w]; Q += sh[8 + w]; }
        sh[0] = S; sh[8] = Q;
    }
    __syncthreads();
    const float mu  = sh[0] * (1.f / (float)D_);
    const float var = sh[8] * (1.f / (float)D_) - mu * mu;
    const float rs  = rsqrtf(var + 1e-5f);
    float4 gv = ((const float4*)g)[t];
    float4 bv = ((const float4*)bb)[t];
    float4 o;
    o.x = (v.x - mu) * rs * gv.x + bv.x;
    o.y = (v.y - mu) * rs * gv.y + bv.y;
    o.z = (v.z - mu) * rs * gv.z + bv.z;
    o.w = (v.w - mu) * rs * gv.w + bv.w;
    ((float4*)(out + (size_t)row * D_))[t] = o;
}

// ---------------------------------------------------------------------------
// Spectral scan: y[t] = A*y[t-1] + rot*u[t]   (A = sigmoid(log_decay)*rot,
// rot = exp(i*tanh(freq)*0.1)).  Exactly the FFT linear convolution.
// ---------------------------------------------------------------------------
__device__ __forceinline__ void get_Arot(const float* ld, const float* fr, int f,
                                         float& ar, float& ai, float& rr, float& ri)
{
    const float decay = 1.f / (1.f + expf(-ld[f]));
    const float om = tanhf(fr[f]) * 0.1f;
    rr = cosf(om); ri = sinf(om);
    ar = decay * rr; ai = decay * ri;
}

__global__ void scan_carry(const float* __restrict__ spec,
                           const float* __restrict__ ld, const float* __restrict__ fr)
{
    const int f = threadIdx.x;
    const int b = blockIdx.x / CCH;
    const int c = blockIdx.x % CCH;
    float ar, ai, rr, ri; get_Arot(ld, fr, f, ar, ai, rr, ri);
    float yr = 0.f, yi = 0.f;
    const float* base = spec + ((size_t)b * S_ + (size_t)c * LCH) * (2 * F_);
    for (int i = 0; i < LCH; i++) {
        const float ur = base[i * (2*F_) + f];
        const float ui = base[i * (2*F_) + F_ + f];
        const float br = rr*ur - ri*ui;
        const float bi = rr*ui + ri*ur;
        const float nr = ar*yr - ai*yi + br;
        const float ni = ar*yi + ai*yr + bi;
        yr = nr; yi = ni;
    }
    g_carry[((size_t)b * CCH + c) * F_ + f] = make_float2(yr, yi);
}

__global__ void scan_prefix(const float* __restrict__ ld, const float* __restrict__ fr)
{
    if (blockIdx.x == 0 && threadIdx.x == 0) g_errsum = 0.0;  // reset for this launch
    const int f = threadIdx.x;
    const int b = blockIdx.x;
    float ar, ai, rr, ri; get_Arot(ld, fr, f, ar, ai, rr, ri);
    // A^LCH  (LCH=64 -> 6 squarings)
    float pr = ar, pi = ai;
#pragma unroll
    for (int j = 0; j < 6; j++) { float t = pr*pr - pi*pi; pi = 2.f*pr*pi; pr = t; }
    float sr = 0.f, si = 0.f;
    for (int c = 0; c < CCH; c++) {
        g_cin[((size_t)b * CCH + c) * F_ + f] = make_float2(sr, si);
        const float2 cv = g_carry[((size_t)b * CCH + c) * F_ + f];
        const float nr = pr*sr - pi*si + cv.x;
        const float ni = pr*si + pi*sr + cv.y;
        sr = nr; si = ni;
    }
}

__global__ void scan_final(const float* __restrict__ spec, float* __restrict__ so,
                           const float* __restrict__ ld, const float* __restrict__ fr)
{
    const int f = threadIdx.x;
    const int b = blockIdx.x / CCH;
    const int c = blockIdx.x % CCH;
    float ar, ai, rr, ri; get_Arot(ld, fr, f, ar, ai, rr, ri);
    const float2 c0 = g_cin[((size_t)b * CCH + c) * F_ + f];
    float yr = c0.x, yi = c0.y;
    const size_t off = ((size_t)b * S_ + (size_t)c * LCH) * (2 * F_);
    const float* base = spec + off;
    float* ob = so + off;
    for (int i = 0; i < LCH; i++) {
        const float ur = base[i * (2*F_) + f];
        const float ui = base[i * (2*F_) + F_ + f];
        const float br = rr*ur - ri*ui;
        const float bi = rr*ui + ri*ur;
        const float nr = ar*yr - ai*yi + br;
        const float ni = ar*yi + ai*yr + bi;
        yr = nr; yi = ni;
        ob[i * (2*F_) + f]      = yr;
        ob[i * (2*F_) + F_ + f] = yi;
    }
}

// ---------------------------------------------------------------------------
// SGEMM:  C[M,N] = A[M,K] * B[N,K]^T, 128x128x16 tiles, 256 thr, 8x8/thread.
// EPI: 0=plain store, 1=error/corrected + err^2 reduce, 2=bias+GELU, 3=bias.
// M,N,K all multiples of 128/16 here, so no bounds checks needed.
// ---------------------------------------------------------------------------
template<int EPI>
__global__ void __launch_bounds__(256)
sgemm(const float* __restrict__ A, const float* __restrict__ Bm,
      float* __restrict__ C, int K, int N,
      const float* __restrict__ bias,
      const float* __restrict__ td,
      const float* __restrict__ ew)
{
    __shared__ float As[16][132];
    __shared__ float Bs[16][132];
    const int tid = threadIdx.x;
    const int m0 = blockIdx.y * 128;
    const int n0 = blockIdx.x * 128;
    const int tr = tid >> 4;          // 0..15
    const int tc = tid & 15;          // 0..15
    const int lrow = tid >> 2;        // 0..63
    const int lk   = (tid & 3) << 2;  // 0,4,8,12
    const float* Ap = A  + (size_t)m0 * K;
    const float* Bp = Bm + (size_t)n0 * K;

    float acc[8][8];
#pragma unroll
    for (int i = 0; i < 8; i++)
#pragma unroll
        for (int j = 0; j < 8; j++) acc[i][j] = 0.f;

    for (int k0 = 0; k0 < K; k0 += 16) {
#pragma unroll
        for (int h = 0; h < 2; h++) {
            const int r = lrow + h * 64;
            const float4 av = *(const float4*)(Ap + (size_t)r * K + k0 + lk);
            As[lk+0][r] = av.x; As[lk+1][r] = av.y; As[lk+2][r] = av.z; As[lk+3][r] = av.w;
            const float4 bv = *(const float4*)(Bp + (size_t)r * K + k0 + lk);
            Bs[lk+0][r] = bv.x; Bs[lk+1][r] = bv.y; Bs[lk+2][r] = bv.z; Bs[lk+3][r] = bv.w;
        }
        __syncthreads();
#pragma unroll
        for (int kk = 0; kk < 16; kk++) {
            float ra[8], rb[8];
            *(float4*)(ra)     = *(const float4*)&As[kk][tr * 8];
            *(float4*)(ra + 4) = *(const float4*)&As[kk][tr * 8 + 4];
            *(float4*)(rb)     = *(const float4*)&Bs[kk][tc * 8];
            *(float4*)(rb + 4) = *(const float4*)&Bs[kk][tc * 8 + 4];
#pragma unroll
            for (int i = 0; i < 8; i++)
#pragma unroll
                for (int j = 0; j < 8; j++)
                    acc[i][j] = fmaf(ra[i], rb[j], acc[i][j]);
        }
        __syncthreads();
    }

    // ---- epilogue ----
    float esum = 0.f;
    float sw = 0.f;
    if (EPI == 1) sw = 1.f / (1.f + expf(-ew[0]));
    float bcol[8];
    if (EPI == 2 || EPI == 3) {
#pragma unroll
        for (int j = 0; j < 8; j++) bcol[j] = bias[n0 + tc * 8 + j];
    }

#pragma unroll
    for (int i = 0; i < 8; i++) {
        const size_t m = (size_t)(m0 + tr * 8 + i);
        float* crow = C + m * N + n0 + tc * 8;
        float v[8];
#pragma unroll
        for (int j = 0; j < 8; j++) v[j] = acc[i][j];

        if (EPI == 1) {
            const float* trow = td + m * N + n0 + tc * 8;
            const float4 t0 = *(const float4*)trow;
            const float4 t1 = *(const float4*)(trow + 4);
            const float tv[8] = {t0.x, t0.y, t0.z, t0.w, t1.x, t1.y, t1.z, t1.w};
#pragma unroll
            for (int j = 0; j < 8; j++) {
                float e = v[j] - tv[j];
                e = fminf(1.f, fmaxf(-1.f, e));
                esum += e * e;
                v[j] = v[j] - sw * e;
            }
        } else if (EPI == 2) {
#pragma unroll
            for (int j = 0; j < 8; j++) {
                const float x = v[j] + bcol[j];
                v[j] = 0.5f * x * (1.f + erff(x * 0.70710678118654752440f));
            }
        } else if (EPI == 3) {
#pragma unroll
            for (int j = 0; j < 8; j++) v[j] += bcol[j];
        }
        *(float4*)crow       = make_float4(v[0], v[1], v[2], v[3]);
        *(float4*)(crow + 4) = make_float4(v[4], v[5], v[6], v[7]);
    }

    if (EPI == 1) {
#pragma unroll
        for (int o = 16; o > 0; o >>= 1) esum += __shfl_down_sync(0xffffffffu, esum, o);
        float* red = &As[0][0];
        if ((tid & 31) == 0) red[tid >> 5] = esum;
        __syncthreads();
        if (tid == 0) {
            float tot = 0.f;
#pragma unroll
            for (int w = 0; w < 8; w++) tot += red[w];
            atomicAdd(&g_errsum, (double)tot);
        }
    }
}

// ---------------------------------------------------------------------------
__global__ void finalize_pe(float* pe)
{
    float v = (float)(g_errsum * (1.0 / ((double)MR * (double)D_)));
    pe[0] = fminf(1.f, fmaxf(0.f, v));
}

// ---------------------------------------------------------------------------
extern "C" void kernel_launch(void* const* d_in, const int* in_sizes, int n_in,
                              void* d_out, int out_size)
{
    const float* bu        = (const float*)d_in[0];
    const float* td        = (const float*)d_in[1];
    const float* W_spec    = (const float*)d_in[2];
    const float* log_decay = (const float*)d_in[3];
    const float* freq      = (const float*)d_in[4];
    const float* W_from    = (const float*)d_in[5];
    const float* ln1_g     = (const float*)d_in[6];
    const float* ln1_b     = (const float*)d_in[7];
    const float* W1        = (const float*)d_in[8];
    const float* b1        = (const float*)d_in[9];
    const float* W2        = (const float*)d_in[10];
    const float* b2        = (const float*)d_in[11];
    const float* ln2_g     = (const float*)d_in[12];
    const float* ln2_b     = (const float*)d_in[13];
    const float* ew        = (const float*)d_in[14];

    static float* p_xn = nullptr;
    static float* p_spec = nullptr;
    static float* p_so = nullptr;
    static float* p_h2 = nullptr;
    if (!p_xn) {
        cudaGetSymbolAddress((void**)&p_xn,   g_xn);
        cudaGetSymbolAddress((void**)&p_spec, g_spec);
        cudaGetSymbolAddress((void**)&p_so,   g_so);
        cudaGetSymbolAddress((void**)&p_h2,   g_h2);
    }

    float* corrected = (float*)d_out;                       // [MR, D]
    float* nextp     = corrected + (size_t)MR * D_;         // [MR, D]
    float* pe        = corrected + 2 * (size_t)MR * D_;     // scalar

    // 1) x = LN1(bottom_up)
    ln_rows<<<MR, 256>>>(bu, ln1_g, ln1_b, p_xn);

    // 2) spectral = xn @ W_spec^T    [MR, 512]
    sgemm<0><<<dim3((2 * F_) / 128, MR / 128), 256>>>(p_xn, W_spec, p_spec, D_, 2 * F_,
                                                      nullptr, nullptr, nullptr);

    // 3) causal complex scan (== FFT convolution)
    scan_carry <<<B_ * CCH, F_>>>(p_spec, log_decay, freq);
    scan_prefix<<<B_,       F_>>>(log_decay, freq);          // also zeroes g_errsum
    scan_final <<<B_ * CCH, F_>>>(p_spec, p_so, log_decay, freq);

    // 4) bu_repr = so @ W_from^T ; error/clip/correct ; err^2 accumulate
    sgemm<1><<<dim3(D_ / 128, MR / 128), 256>>>(p_so, W_from, corrected, 2 * F_, D_,
                                                nullptr, td, ew);

    // 5) h = gelu(corrected @ W1^T + b1)   (reuse g_xn)
    sgemm<2><<<dim3(D_ / 128, MR / 128), 256>>>(corrected, W1, p_xn, D_, D_,
                                                b1, nullptr, nullptr);

    // 6) h2 = h @ W2^T + b2
    sgemm<3><<<dim3(D_ / 128, MR / 128), 256>>>(p_xn, W2, p_h2, D_, D_,
                                                b2, nullptr, nullptr);

    // 7) next_prediction = LN2(h2)
    ln_rows<<<MR, 256>>>(p_h2, ln2_g, ln2_b, nextp);

    // 8) prediction_error scalar
    finalize_pe<<<1, 1>>>(pe);
}

// round 7
// speedup vs baseline: 2.0338x; 2.0338x over previous
#include <cuda_runtime.h>
#include <cuda_bf16.h>
#include <math.h>
#include <stdint.h>

#define B_   4
#define S_   4096
#define D_   1024
#define F_   256
#define MR   (B_*S_)        // 16384 rows
#define CCH  64
#define LCH  (S_/CCH)

typedef __nv_bfloat16 bf16;

// ---------------------------------------------------------------------------
// Device scratch (no allocations allowed)
// ---------------------------------------------------------------------------
__device__ bf16   g_xn_hi[MR * D_];
__device__ bf16   g_xn_lo[MR * D_];
__device__ float  g_spec [MR * 2 * F_];
__device__ bf16   g_so_hi[MR * 2 * F_];
__device__ bf16   g_so_lo[MR * 2 * F_];
__device__ bf16   g_co_hi[MR * D_];
__device__ bf16   g_co_lo[MR * D_];
__device__ bf16   g_h_hi [MR * D_];
__device__ bf16   g_h_lo [MR * D_];
__device__ float  g_h2   [MR * D_];
__device__ bf16   g_ws_hi[2 * F_ * D_];
__device__ bf16   g_ws_lo[2 * F_ * D_];
__device__ bf16   g_wf_hi[D_ * 2 * F_];
__device__ bf16   g_wf_lo[D_ * 2 * F_];
__device__ bf16   g_w1_hi[D_ * D_];
__device__ bf16   g_w1_lo[D_ * D_];
__device__ bf16   g_w2_hi[D_ * D_];
__device__ bf16   g_w2_lo[D_ * D_];
__device__ float2 g_carry[B_ * CCH * F_];
__device__ float2 g_cin  [B_ * CCH * F_];
__device__ double g_errsum;

// ---------------------------------------------------------------------------
// PTX helpers (compute_103-safe: cp.async + ldmatrix + mma.sync only)
// ---------------------------------------------------------------------------
__device__ __forceinline__ uint32_t smem_u32(const void* p) {
    uint32_t a;
    asm("{ .reg .u64 t; cvta.to.shared.u64 t, %1; cvt.u32.u64 %0, t; }" : "=r"(a) : "l"(p));
    return a;
}
__device__ __forceinline__ void cp16(uint32_t sa, const void* ga) {
    asm volatile("cp.async.cg.shared.global [%0], [%1], 16;" :: "r"(sa), "l"(ga) : "memory");
}
#define CP_COMMIT() asm volatile("cp.async.commit_group;" ::: "memory")
#define CP_WAIT1()  asm volatile("cp.async.wait_group 1;" ::: "memory")

__device__ __forceinline__ void ldsm4(uint32_t* r, uint32_t a) {
    asm volatile("ldmatrix.sync.aligned.m8n8.x4.shared.b16 {%0,%1,%2,%3}, [%4];"
        : "=r"(r[0]), "=r"(r[1]), "=r"(r[2]), "=r"(r[3]) : "r"(a));
}
__device__ __forceinline__ void ldsm2(uint32_t* r, uint32_t a) {
    asm volatile("ldmatrix.sync.aligned.m8n8.x2.shared.b16 {%0,%1}, [%2];"
        : "=r"(r[0]), "=r"(r[1]) : "r"(a));
}
__device__ __forceinline__ void mma16816(float* c, const uint32_t* a, const uint32_t* b) {
    asm volatile("mma.sync.aligned.m16n8k16.row.col.f32.bf16.bf16.f32 "
        "{%0,%1,%2,%3}, {%4,%5,%6,%7}, {%8,%9}, {%0,%1,%2,%3};"
        : "+f"(c[0]), "+f"(c[1]), "+f"(c[2]), "+f"(c[3])
        : "r"(a[0]), "r"(a[1]), "r"(a[2]), "r"(a[3]), "r"(b[0]), "r"(b[1]));
}

// ---------------------------------------------------------------------------
// bf16 split helpers
// ---------------------------------------------------------------------------
__device__ __forceinline__ uint32_t pksplit(float a, float b, uint32_t& lo) {
    bf16 ha = __float2bfloat16(a), hb = __float2bfloat16(b);
    bf16 la = __float2bfloat16(a - __bfloat162float(ha));
    bf16 lb = __float2bfloat16(b - __bfloat162float(hb));
    lo = ((uint32_t)__bfloat16_as_ushort(lb) << 16) | (uint32_t)__bfloat16_as_ushort(la);
    return ((uint32_t)__bfloat16_as_ushort(hb) << 16) | (uint32_t)__bfloat16_as_ushort(ha);
}

__global__ void wsplit(const float* __restrict__ w, bf16* __restrict__ hi,
                       bf16* __restrict__ lo, int n)
{
    const int i4 = (blockIdx.x * blockDim.x + threadIdx.x) * 4;
    if (i4 >= n) return;
    float4 v = *(const float4*)(w + i4);
    uint32_t l0, l1;
    uint32_t h0 = pksplit(v.x, v.y, l0);
    uint32_t h1 = pksplit(v.z, v.w, l1);
    *(uint2*)(hi + i4) = make_uint2(h0, h1);
    *(uint2*)(lo + i4) = make_uint2(l0, l1);
}

// ---------------------------------------------------------------------------
// LayerNorm (row of 1024, 256 threads). SPLIT=1: bf16 hi/lo out, else fp32.
// ---------------------------------------------------------------------------
template<int SPLIT>
__global__ void ln_rows(const float* __restrict__ x, const float* __restrict__ g,
                        const float* __restrict__ bb, float* __restrict__ outf,
                        bf16* __restrict__ oh, bf16* __restrict__ ol)
{
    __shared__ float sh[16];
    const int row = blockIdx.x;
    const int t   = threadIdx.x;
    const float4* xr = (const float4*)(x + (size_t)row * D_);
    float4 v = xr[t];
    float s = v.x + v.y + v.z + v.w;
    float q = v.x*v.x + v.y*v.y + v.z*v.z + v.w*v.w;
#pragma unroll
    for (int o = 16; o > 0; o >>= 1) {
        s += __shfl_down_sync(0xffffffffu, s, o);
        q += __shfl_down_sync(0xffffffffu, q, o);
    }
    if ((t & 31) == 0) { sh[t >> 5] = s; sh[8 + (t >> 5)] = q; }
    __syncthreads();
    if (t == 0) {
        float S = 0.f, Q = 0.f;
#pragma unroll
        for (int w = 0; w < 8; w++) { S += sh[w]; Q += sh[8 + w]; }
        sh[0] = S; sh[8] = Q;
    }
    __syncthreads();
    const float mu  = sh[0] * (1.f / (float)D_);
    const float var = sh[8] * (1.f / (float)D_) - mu * mu;
    const float rs  = rsqrtf(var + 1e-5f);
    float4 gv = ((const float4*)g)[t];
    float4 bv = ((const float4*)bb)[t];
    float4 o;
    o.x = (v.x - mu) * rs * gv.x + bv.x;
    o.y = (v.y - mu) * rs * gv.y + bv.y;
    o.z = (v.z - mu) * rs * gv.z + bv.z;
    o.w = (v.w - mu) * rs * gv.w + bv.w;
    if (SPLIT) {
        uint32_t l0, l1;
        uint32_t h0 = pksplit(o.x, o.y, l0);
        uint32_t h1 = pksplit(o.z, o.w, l1);
        ((uint2*)(oh + (size_t)row * D_))[t] = make_uint2(h0, h1);
        ((uint2*)(ol + (size_t)row * D_))[t] = make_uint2(l0, l1);
    } else {
        ((float4*)(outf + (size_t)row * D_))[t] = o;
    }
}

// ---------------------------------------------------------------------------
// Spectral scan (== the FFT causal convolution)
// ---------------------------------------------------------------------------
__device__ __forceinline__ void get_Arot(const float* ld, const float* fr, int f,
                                         float& ar, float& ai, float& rr, float& ri)
{
    const float decay = 1.f / (1.f + expf(-ld[f]));
    const float om = tanhf(fr[f]) * 0.1f;
    rr = cosf(om); ri = sinf(om);
    ar = decay * rr; ai = decay * ri;
}

__global__ void scan_carry(const float* __restrict__ spec,
                           const float* __restrict__ ld, const float* __restrict__ fr)
{
    const int f = threadIdx.x;
    const int b = blockIdx.x / CCH;
    const int c = blockIdx.x % CCH;
    float ar, ai, rr, ri; get_Arot(ld, fr, f, ar, ai, rr, ri);
    float yr = 0.f, yi = 0.f;
    const float* base = spec + ((size_t)b * S_ + (size_t)c * LCH) * (2 * F_);
    for (int i = 0; i < LCH; i++) {
        const float ur = base[i * (2*F_) + f];
        const float ui = base[i * (2*F_) + F_ + f];
        const float br = rr*ur - ri*ui;
        const float bi = rr*ui + ri*ur;
        const float nr = ar*yr - ai*yi + br;
        const float ni = ar*yi + ai*yr + bi;
        yr = nr; yi = ni;
    }
    g_carry[((size_t)b * CCH + c) * F_ + f] = make_float2(yr, yi);
}

__global__ void scan_prefix(const float* __restrict__ ld, const float* __restrict__ fr)
{
    if (blockIdx.x == 0 && threadIdx.x == 0) g_errsum = 0.0;
    const int f = threadIdx.x;
    const int b = blockIdx.x;
    float ar, ai, rr, ri; get_Arot(ld, fr, f, ar, ai, rr, ri);
    float pr = ar, pi = ai;
#pragma unroll
    for (int j = 0; j < 6; j++) { float t = pr*pr - pi*pi; pi = 2.f*pr*pi; pr = t; }
    float sr = 0.f, si = 0.f;
    for (int c = 0; c < CCH; c++) {
        g_cin[((size_t)b * CCH + c) * F_ + f] = make_float2(sr, si);
        const float2 cv = g_carry[((size_t)b * CCH + c) * F_ + f];
        const float nr = pr*sr - pi*si + cv.x;
        const float ni = pr*si + pi*sr + cv.y;
        sr = nr; si = ni;
    }
}

__global__ void scan_final(const float* __restrict__ spec,
                           bf16* __restrict__ soh, bf16* __restrict__ sol,
                           const float* __restrict__ ld, const float* __restrict__ fr)
{
    const int f = threadIdx.x;
    const int b = blockIdx.x / CCH;
    const int c = blockIdx.x % CCH;
    float ar, ai, rr, ri; get_Arot(ld, fr, f, ar, ai, rr, ri);
    const float2 c0 = g_cin[((size_t)b * CCH + c) * F_ + f];
    float yr = c0.x, yi = c0.y;
    const size_t off = ((size_t)b * S_ + (size_t)c * LCH) * (2 * F_);
    const float* base = spec + off;
    for (int i = 0; i < LCH; i++) {
        const float ur = base[i * (2*F_) + f];
        const float ui = base[i * (2*F_) + F_ + f];
        const float br = rr*ur - ri*ui;
        const float bi = rr*ui + ri*ur;
        const float nr = ar*yr - ai*yi + br;
        const float ni = ar*yi + ai*yr + bi;
        yr = nr; yi = ni;
        const size_t pr_ = off + i * (2*F_) + f;
        const size_t pi_ = pr_ + F_;
        bf16 hr = __float2bfloat16(yr);
        bf16 hi_ = __float2bfloat16(yi);
        soh[pr_] = hr;  sol[pr_] = __float2bfloat16(yr - __bfloat162float(hr));
        soh[pi_] = hi_; sol[pi_] = __float2bfloat16(yi - __bfloat162float(hi_));
    }
}

// ---------------------------------------------------------------------------
// mma.sync split-bf16 GEMM: C[M,N] = A[M,K] * B[N,K]^T  (fp32-accurate)
// CTA 128x128, 8 warps (2m x 4n), warp tile 64x32, K-chunk 32, cp.async x2.
// Smem per stage: 4 tiles (Ah,Al,Bh,Bl), each 128 rows x 32 bf16, padded to
// 40 bf16 (80B) per row -> conflict-free ldmatrix.
// EPI: 0 = fp32 store; 1 = error/corrected (+err^2) fp32 + split out;
//      2 = bias+GELU split out; 3 = bias fp32 out.
// ---------------------------------------------------------------------------
#define ROWB     80            // padded row stride (bytes)
#define TILE_SZ  (128 * ROWB)  // 10240
#define STAGE_SZ (4 * TILE_SZ) // 40960
#define SMEM_TOT (2 * STAGE_SZ)

__device__ __forceinline__ void stage_load(char* sm, const bf16* __restrict__ Ah,
                                           const bf16* __restrict__ Al,
                                           const bf16* __restrict__ Bh,
                                           const bf16* __restrict__ Bl,
                                           int K, int k0, int tid)
{
    const bf16* gp[4] = { Ah + k0, Al + k0, Bh + k0, Bl + k0 };
#pragma unroll
    for (int t = 0; t < 4; t++) {
        uint32_t sbase = smem_u32(sm + t * TILE_SZ);
        const char* G = (const char*)gp[t];
#pragma unroll
        for (int i = 0; i < 2; i++) {
            const int idx = tid + i * 256;
            const int row = idx >> 2, cc = idx & 3;
            cp16(sbase + row * ROWB + cc * 16,
                 G + ((size_t)row * K + cc * 8) * 2);
        }
    }
}

template<int EPI>
__global__ void __launch_bounds__(256, 1)
tgemm(const bf16* __restrict__ Ahi, const bf16* __restrict__ Alo,
      const bf16* __restrict__ Bhi, const bf16* __restrict__ Blo,
      int K, int N,
      float* __restrict__ Cf,
      bf16* __restrict__ Chi, bf16* __restrict__ Clo,
      const float* __restrict__ bias,
      const float* __restrict__ td,
      const float* __restrict__ ew)
{
    extern __shared__ char smem[];
    const int tid = threadIdx.x;
    const int w = tid >> 5, lid = tid & 31;
    const int wm = w & 1, wn = w >> 1;
    const int m0 = blockIdx.y * 128;
    const int n0 = blockIdx.x * 128;

    const bf16* Ah = Ahi + (size_t)m0 * K;
    const bf16* Al = Alo + (size_t)m0 * K;
    const bf16* Bh = Bhi + (size_t)n0 * K;
    const bf16* Bl = Blo + (size_t)n0 * K;

    float acc[4][4][4];
#pragma unroll
    for (int i = 0; i < 4; i++)
#pragma unroll
        for (int j = 0; j < 4; j++)
#pragma unroll
            for (int k = 0; k < 4; k++) acc[i][j][k] = 0.f;

    const uint32_t sb = smem_u32(smem);
    const int NC = K >> 5;

    stage_load(smem, Ah, Al, Bh, Bl, K, 0, tid);
    CP_COMMIT();

    for (int c = 0; c < NC; c++) {
        if (c + 1 < NC)
            stage_load(smem + ((c + 1) & 1) * STAGE_SZ, Ah, Al, Bh, Bl, K, (c + 1) << 5, tid);
        CP_COMMIT();
        CP_WAIT1();
        __syncthreads();

        const uint32_t st = sb + (c & 1) * STAGE_SZ;
#pragma unroll
        for (int ks = 0; ks < 2; ks++) {
            uint32_t ah[4][4], al[4][4], bh[4][2], bl[4][2];
#pragma unroll
            for (int mf = 0; mf < 4; mf++) {
                const uint32_t ra = st + (wm * 64 + mf * 16 + (lid & 15)) * ROWB
                                       + (ks * 2 + (lid >> 4)) * 16;
                ldsm4(ah[mf], ra);
                ldsm4(al[mf], ra + TILE_SZ);
            }
#pragma unroll
            for (int nf = 0; nf < 4; nf++) {
                const uint32_t rb = st + 2 * TILE_SZ
                                       + (wn * 32 + nf * 8 + (lid & 7)) * ROWB
                                       + (ks * 2 + ((lid >> 3) & 1)) * 16;
                ldsm2(bh[nf], rb);
                ldsm2(bl[nf], rb + TILE_SZ);
            }
#pragma unroll
            for (int mf = 0; mf < 4; mf++)
#pragma unroll
                for (int nf = 0; nf < 4; nf++) {
                    mma16816(acc[mf][nf], ah[mf], bh[nf]);
                    mma16816(acc[mf][nf], ah[mf], bl[nf]);
                    mma16816(acc[mf][nf], al[mf], bh[nf]);
                }
        }
        __syncthreads();
    }

    // ---- epilogue ----
    const int lrow = lid >> 2;
    const int lcol = (lid & 3) * 2;
    float sw = 0.f, esum = 0.f;
    if (EPI == 1) sw = 1.f / (1.f + expf(-ew[0]));

#pragma unroll
    for (int mf = 0; mf < 4; mf++) {
#pragma unroll
        for (int half = 0; half < 2; half++) {
            const int m = m0 + wm * 64 + mf * 16 + lrow + half * 8;
#pragma unroll
            for (int nf = 0; nf < 4; nf++) {
                const int n = n0 + wn * 32 + nf * 8 + lcol;
                float v0 = acc[mf][nf][half * 2 + 0];
                float v1 = acc[mf][nf][half * 2 + 1];

                if (EPI == 1) {
                    const float2 t2 = *(const float2*)(td + (size_t)m * N + n);
                    float e0 = fminf(1.f, fmaxf(-1.f, v0 - t2.x));
                    float e1 = fminf(1.f, fmaxf(-1.f, v1 - t2.y));
                    esum += e0 * e0 + e1 * e1;
                    v0 -= sw * e0;
                    v1 -= sw * e1;
                } else if (EPI == 2 || EPI == 3) {
                    const float2 b2 = *(const float2*)(bias + n);
                    v0 += b2.x; v1 += b2.y;
                    if (EPI == 2) {
                        v0 = 0.5f * v0 * (1.f + erff(v0 * 0.70710678118654752440f));
                        v1 = 0.5f * v1 * (1.f + erff(v1 * 0.70710678118654752440f));
                    }
                }

                if (EPI != 2)
                    *(float2*)(Cf + (size_t)m * N + n) = make_float2(v0, v1);
                if (EPI == 1 || EPI == 2) {
                    uint32_t lo;
                    const uint32_t hi = pksplit(v0, v1, lo);
                    *(uint32_t*)(Chi + (size_t)m * N + n) = hi;
                    *(uint32_t*)(Clo + (size_t)m * N + n) = lo;
                }
            }
        }
    }

    if (EPI == 1) {
#pragma unroll
        for (int o = 16; o > 0; o >>= 1) esum += __shfl_down_sync(0xffffffffu, esum, o);
        if (lid == 0) atomicAdd(&g_errsum, (double)esum);
    }
}

// ---------------------------------------------------------------------------
__global__ void finalize_pe(float* pe)
{
    float v = (float)(g_errsum * (1.0 / ((double)MR * (double)D_)));
    pe[0] = fminf(1.f, fmaxf(0.f, v));
}

// ---------------------------------------------------------------------------
extern "C" void kernel_launch(void* const* d_in, const int* in_sizes, int n_in,
                              void* d_out, int out_size)
{
    const float* bu        = (const float*)d_in[0];
    const float* td        = (const float*)d_in[1];
    const float* W_spec    = (const float*)d_in[2];
    const float* log_decay = (const float*)d_in[3];
    const float* freq      = (const float*)d_in[4];
    const float* W_from    = (const float*)d_in[5];
    const float* ln1_g     = (const float*)d_in[6];
    const float* ln1_b     = (const float*)d_in[7];
    const float* W1        = (const float*)d_in[8];
    const float* b1        = (const float*)d_in[9];
    const float* W2        = (const float*)d_in[10];
    const float* b2        = (const float*)d_in[11];
    const float* ln2_g     = (const float*)d_in[12];
    const float* ln2_b     = (const float*)d_in[13];
    const float* ew        = (const float*)d_in[14];

    static bool inited = false;
    static bf16 *xnh, *xnl, *soh, *sol, *coh, *col_, *hh, *hl;
    static bf16 *wsh, *wsl, *wfh, *wfl, *w1h, *w1l, *w2h, *w2l;
    static float *p_spec, *p_h2;
    if (!inited) {
        cudaGetSymbolAddress((void**)&xnh,  g_xn_hi);  cudaGetSymbolAddress((void**)&xnl,  g_xn_lo);
        cudaGetSymbolAddress((void**)&soh,  g_so_hi);  cudaGetSymbolAddress((void**)&sol,  g_so_lo);
        cudaGetSymbolAddress((void**)&coh,  g_co_hi);  cudaGetSymbolAddress((void**)&col_, g_co_lo);
        cudaGetSymbolAddress((void**)&hh,   g_h_hi);   cudaGetSymbolAddress((void**)&hl,   g_h_lo);
        cudaGetSymbolAddress((void**)&wsh,  g_ws_hi);  cudaGetSymbolAddress((void**)&wsl,  g_ws_lo);
        cudaGetSymbolAddress((void**)&wfh,  g_wf_hi);  cudaGetSymbolAddress((void**)&wfl,  g_wf_lo);
        cudaGetSymbolAddress((void**)&w1h,  g_w1_hi);  cudaGetSymbolAddress((void**)&w1l,  g_w1_lo);
        cudaGetSymbolAddress((void**)&w2h,  g_w2_hi);  cudaGetSymbolAddress((void**)&w2l,  g_w2_lo);
        cudaGetSymbolAddress((void**)&p_spec, g_spec);
        cudaGetSymbolAddress((void**)&p_h2,   g_h2);
        cudaFuncSetAttribute(tgemm<0>, cudaFuncAttributeMaxDynamicSharedMemorySize, SMEM_TOT);
        cudaFuncSetAttribute(tgemm<1>, cudaFuncAttributeMaxDynamicSharedMemorySize, SMEM_TOT);
        cudaFuncSetAttribute(tgemm<2>, cudaFuncAttributeMaxDynamicSharedMemorySize, SMEM_TOT);
        cudaFuncSetAttribute(tgemm<3>, cudaFuncAttributeMaxDynamicSharedMemorySize, SMEM_TOT);
        inited = true;
    }

    float* corrected = (float*)d_out;
    float* nextp     = corrected + (size_t)MR * D_;
    float* pe        = corrected + 2 * (size_t)MR * D_;

    // weight splits
    wsplit<<<(2 * F_ * D_) / 1024, 256>>>(W_spec, wsh, wsl, 2 * F_ * D_);
    wsplit<<<(D_ * 2 * F_) / 1024, 256>>>(W_from, wfh, wfl, D_ * 2 * F_);
    wsplit<<<(D_ * D_) / 1024, 256>>>(W1, w1h, w1l, D_ * D_);
    wsplit<<<(D_ * D_) / 1024, 256>>>(W2, w2h, w2l, D_ * D_);

    // 1) LN1 -> bf16 split
    ln_rows<1><<<MR, 256>>>(bu, ln1_g, ln1_b, nullptr, xnh, xnl);

    // 2) spectral = xn @ W_spec^T  [MR, 512] fp32
    tgemm<0><<<dim3((2 * F_) / 128, MR / 128), 256, SMEM_TOT>>>(
        xnh, xnl, wsh, wsl, D_, 2 * F_, p_spec, nullptr, nullptr,
        nullptr, nullptr, nullptr);

    // 3) causal complex scan (== FFT convolution)
    scan_carry <<<B_ * CCH, F_>>>(p_spec, log_decay, freq);
    scan_prefix<<<B_,       F_>>>(log_decay, freq);
    scan_final <<<B_ * CCH, F_>>>(p_spec, soh, sol, log_decay, freq);

    // 4) corrected = so @ W_from^T - sw*clip(...)   (+err^2)
    tgemm<1><<<dim3(D_ / 128, MR / 128), 256, SMEM_TOT>>>(
        soh, sol, wfh, wfl, 2 * F_, D_, corrected, coh, col_,
        nullptr, td, ew);

    // 5) h = gelu(corrected @ W1^T + b1) -> bf16 split
    tgemm<2><<<dim3(D_ / 128, MR / 128), 256, SMEM_TOT>>>(
        coh, col_, w1h, w1l, D_, D_, nullptr, hh, hl,
        b1, nullptr, nullptr);

    // 6) h2 = h @ W2^T + b2
    tgemm<3><<<dim3(D_ / 128, MR / 128), 256, SMEM_TOT>>>(
        hh, hl, w2h, w2l, D_, D_, p_h2, nullptr, nullptr,
        b2, nullptr, nullptr);

    // 7) next_prediction = LN2(h2)
    ln_rows<0><<<MR, 256>>>(p_h2, ln2_g, ln2_b, nextp, nullptr, nullptr);

    // 8) scalar
    finalize_pe<<<1, 1>>>(pe);
}

// round 10
// speedup vs baseline: 2.0896x; 1.0274x over previous
#include <cuda_runtime.h>
#include <cuda_bf16.h>
#include <math.h>
#include <stdint.h>

#define B_   4
#define S_   4096
#define D_   1024
#define F_   256
#define MR   (B_*S_)        // 16384 rows
#define CCH  64
#define LCH  (S_/CCH)

typedef __nv_bfloat16 bf16;

// ---------------------------------------------------------------------------
// Device scratch (no allocations allowed)
// ---------------------------------------------------------------------------
__device__ bf16   g_xn_hi[MR * D_];
__device__ bf16   g_xn_lo[MR * D_];
__device__ float  g_spec [MR * 2 * F_];
__device__ bf16   g_so_hi[MR * 2 * F_];
__device__ bf16   g_so_lo[MR * 2 * F_];
__device__ bf16   g_co_hi[MR * D_];
__device__ bf16   g_co_lo[MR * D_];
__device__ bf16   g_h_hi [MR * D_];
__device__ bf16   g_h_lo [MR * D_];
__device__ float  g_h2   [MR * D_];
__device__ bf16   g_ws_hi[2 * F_ * D_];
__device__ bf16   g_ws_lo[2 * F_ * D_];
__device__ bf16   g_wf_hi[D_ * 2 * F_];
__device__ bf16   g_wf_lo[D_ * 2 * F_];
__device__ bf16   g_w1_hi[D_ * D_];
__device__ bf16   g_w1_lo[D_ * D_];
__device__ bf16   g_w2_hi[D_ * D_];
__device__ bf16   g_w2_lo[D_ * D_];
__device__ float2 g_carry[B_ * CCH * F_];
__device__ float2 g_cin  [B_ * CCH * F_];
__device__ double g_errsum;

// ---------------------------------------------------------------------------
// PTX helpers (compute_103-safe: cp.async + ldmatrix + mma.sync only)
// ---------------------------------------------------------------------------
__device__ __forceinline__ uint32_t smem_u32(const void* p) {
    uint32_t a;
    asm("{ .reg .u64 t; cvta.to.shared.u64 t, %1; cvt.u32.u64 %0, t; }" : "=r"(a) : "l"(p));
    return a;
}
__device__ __forceinline__ void cp16(uint32_t sa, const void* ga) {
    asm volatile("cp.async.cg.shared.global [%0], [%1], 16;" :: "r"(sa), "l"(ga) : "memory");
}
#define CP_COMMIT() asm volatile("cp.async.commit_group;" ::: "memory")
#define CP_WAIT1()  asm volatile("cp.async.wait_group 1;" ::: "memory")

__device__ __forceinline__ void ldsm4(uint32_t* r, uint32_t a) {
    asm volatile("ldmatrix.sync.aligned.m8n8.x4.shared.b16 {%0,%1,%2,%3}, [%4];"
        : "=r"(r[0]), "=r"(r[1]), "=r"(r[2]), "=r"(r[3]) : "r"(a));
}
__device__ __forceinline__ void mma16816(float* c, const uint32_t* a, const uint32_t* b) {
    asm volatile("mma.sync.aligned.m16n8k16.row.col.f32.bf16.bf16.f32 "
        "{%0,%1,%2,%3}, {%4,%5,%6,%7}, {%8,%9}, {%0,%1,%2,%3};"
        : "+f"(c[0]), "+f"(c[1]), "+f"(c[2]), "+f"(c[3])
        : "r"(a[0]), "r"(a[1]), "r"(a[2]), "r"(a[3]), "r"(b[0]), "r"(b[1]));
}

// ---------------------------------------------------------------------------
// bf16 split helpers
// ---------------------------------------------------------------------------
__device__ __forceinline__ uint32_t pksplit(float a, float b, uint32_t& lo) {
    bf16 ha = __float2bfloat16(a), hb = __float2bfloat16(b);
    bf16 la = __float2bfloat16(a - __bfloat162float(ha));
    bf16 lb = __float2bfloat16(b - __bfloat162float(hb));
    lo = ((uint32_t)__bfloat16_as_ushort(lb) << 16) | (uint32_t)__bfloat16_as_ushort(la);
    return ((uint32_t)__bfloat16_as_ushort(hb) << 16) | (uint32_t)__bfloat16_as_ushort(ha);
}

__global__ void wsplit(const float* __restrict__ w, bf16* __restrict__ hi,
                       bf16* __restrict__ lo, int n)
{
    const int i4 = (blockIdx.x * blockDim.x + threadIdx.x) * 4;
    if (i4 >= n) return;
    float4 v = *(const float4*)(w + i4);
    uint32_t l0, l1;
    uint32_t h0 = pksplit(v.x, v.y, l0);
    uint32_t h1 = pksplit(v.z, v.w, l1);
    *(uint2*)(hi + i4) = make_uint2(h0, h1);
    *(uint2*)(lo + i4) = make_uint2(l0, l1);
}

// ---------------------------------------------------------------------------
// LayerNorm (row of 1024, 256 threads). SPLIT=1: bf16 hi/lo out, else fp32.
// ---------------------------------------------------------------------------
template<int SPLIT>
__global__ void ln_rows(const float* __restrict__ x, const float* __restrict__ g,
                        const float* __restrict__ bb, float* __restrict__ outf,
                        bf16* __restrict__ oh, bf16* __restrict__ ol)
{
    __shared__ float sh[16];
    const int row = blockIdx.x;
    const int t   = threadIdx.x;
    const float4* xr = (const float4*)(x + (size_t)row * D_);
    float4 v = xr[t];
    float s = v.x + v.y + v.z + v.w;
    float q = v.x*v.x + v.y*v.y + v.z*v.z + v.w*v.w;
#pragma unroll
    for (int o = 16; o > 0; o >>= 1) {
        s += __shfl_down_sync(0xffffffffu, s, o);
        q += __shfl_down_sync(0xffffffffu, q, o);
    }
    if ((t & 31) == 0) { sh[t >> 5] = s; sh[8 + (t >> 5)] = q; }
    __syncthreads();
    if (t == 0) {
        float S = 0.f, Q = 0.f;
#pragma unroll
        for (int w = 0; w < 8; w++) { S += sh[w]; Q += sh[8 + w]; }
        sh[0] = S; sh[8] = Q;
    }
    __syncthreads();
    const float mu  = sh[0] * (1.f / (float)D_);
    const float var = sh[8] * (1.f / (float)D_) - mu * mu;
    const float rs  = rsqrtf(var + 1e-5f);
    float4 gv = ((const float4*)g)[t];
    float4 bv = ((const float4*)bb)[t];
    float4 o;
    o.x = (v.x - mu) * rs * gv.x + bv.x;
    o.y = (v.y - mu) * rs * gv.y + bv.y;
    o.z = (v.z - mu) * rs * gv.z + bv.z;
    o.w = (v.w - mu) * rs * gv.w + bv.w;
    if (SPLIT) {
        uint32_t l0, l1;
        uint32_t h0 = pksplit(o.x, o.y, l0);
        uint32_t h1 = pksplit(o.z, o.w, l1);
        ((uint2*)(oh + (size_t)row * D_))[t] = make_uint2(h0, h1);
        ((uint2*)(ol + (size_t)row * D_))[t] = make_uint2(l0, l1);
    } else {
        ((float4*)(outf + (size_t)row * D_))[t] = o;
    }
}

// ---------------------------------------------------------------------------
// Spectral scan (== the FFT causal convolution)
// ---------------------------------------------------------------------------
__device__ __forceinline__ void get_Arot(const float* ld, const float* fr, int f,
                                         float& ar, float& ai, float& rr, float& ri)
{
    const float decay = 1.f / (1.f + expf(-ld[f]));
    const float om = tanhf(fr[f]) * 0.1f;
    rr = cosf(om); ri = sinf(om);
    ar = decay * rr; ai = decay * ri;
}

__global__ void scan_carry(const float* __restrict__ spec,
                           const float* __restrict__ ld, const float* __restrict__ fr)
{
    const int f = threadIdx.x;
    const int b = blockIdx.x / CCH;
    const int c = blockIdx.x % CCH;
    float ar, ai, rr, ri; get_Arot(ld, fr, f, ar, ai, rr, ri);
    float yr = 0.f, yi = 0.f;
    const float* base = spec + ((size_t)b * S_ + (size_t)c * LCH) * (2 * F_);
    for (int i = 0; i < LCH; i++) {
        const float ur = base[i * (2*F_) + f];
        const float ui = base[i * (2*F_) + F_ + f];
        const float br = rr*ur - ri*ui;
        const float bi = rr*ui + ri*ur;
        const float nr = ar*yr - ai*yi + br;
        const float ni = ar*yi + ai*yr + bi;
        yr = nr; yi = ni;
    }
    g_carry[((size_t)b * CCH + c) * F_ + f] = make_float2(yr, yi);
}

__global__ void scan_prefix(const float* __restrict__ ld, const float* __restrict__ fr)
{
    if (blockIdx.x == 0 && threadIdx.x == 0) g_errsum = 0.0;
    const int f = threadIdx.x;
    const int b = blockIdx.x;
    float ar, ai, rr, ri; get_Arot(ld, fr, f, ar, ai, rr, ri);
    float pr = ar, pi = ai;
#pragma unroll
    for (int j = 0; j < 6; j++) { float t = pr*pr - pi*pi; pi = 2.f*pr*pi; pr = t; }
    float sr = 0.f, si = 0.f;
    for (int c = 0; c < CCH; c++) {
        g_cin[((size_t)b * CCH + c) * F_ + f] = make_float2(sr, si);
        const float2 cv = g_carry[((size_t)b * CCH + c) * F_ + f];
        const float nr = pr*sr - pi*si + cv.x;
        const float ni = pr*si + pi*sr + cv.y;
        sr = nr; si = ni;
    }
}

__global__ void scan_final(const float* __restrict__ spec,
                           bf16* __restrict__ soh, bf16* __restrict__ sol,
                           const float* __restrict__ ld, const float* __restrict__ fr)
{
    const int f = threadIdx.x;
    const int b = blockIdx.x / CCH;
    const int c = blockIdx.x % CCH;
    float ar, ai, rr, ri; get_Arot(ld, fr, f, ar, ai, rr, ri);
    const float2 c0 = g_cin[((size_t)b * CCH + c) * F_ + f];
    float yr = c0.x, yi = c0.y;
    const size_t off = ((size_t)b * S_ + (size_t)c * LCH) * (2 * F_);
    const float* base = spec + off;
    for (int i = 0; i < LCH; i++) {
        const float ur = base[i * (2*F_) + f];
        const float ui = base[i * (2*F_) + F_ + f];
        const float br = rr*ur - ri*ui;
        const float bi = rr*ui + ri*ur;
        const float nr = ar*yr - ai*yi + br;
        const float ni = ar*yi + ai*yr + bi;
        yr = nr; yi = ni;
        const size_t pr_ = off + i * (2*F_) + f;
        const size_t pi_ = pr_ + F_;
        bf16 hr = __float2bfloat16(yr);
        bf16 hi_ = __float2bfloat16(yi);
        soh[pr_] = hr;  sol[pr_] = __float2bfloat16(yr - __bfloat162float(hr));
        soh[pi_] = hi_; sol[pi_] = __float2bfloat16(yi - __bfloat162float(hi_));
    }
}

// ---------------------------------------------------------------------------
// mma.sync split-bf16 GEMM: C[M,N] = A[M,K] * B[N,K]^T  (fp32-accurate)
// CTA 128x256, 8 warps (2m x 4n), warp tile 64x64, K-chunk 32, cp.async x2.
// Smem per stage: A hi/lo (128 rows) + B hi/lo (256 rows), 32 bf16/row padded
// to 80 B -> conflict-free ldmatrix (banks 20r mod 32 distinct over 8 rows).
// EPI: 0 = fp32 store; 1 = error/corrected (+err^2) fp32 + split out;
//      2 = bias+GELU split out; 3 = bias fp32 out.
// ---------------------------------------------------------------------------
#define ROWB     80              // padded row stride (bytes)
#define A_TILE   (128 * ROWB)    // 10240
#define B_TILE   (256 * ROWB)    // 20480
#define OFF_AH   0
#define OFF_AL   A_TILE
#define OFF_BH   (2 * A_TILE)
#define OFF_BL   (2 * A_TILE + B_TILE)
#define STAGE_SZ (2 * A_TILE + 2 * B_TILE)   // 61440
#define SMEM_TOT (2 * STAGE_SZ)              // 122880

__device__ __forceinline__ void stage_load(char* sm, const bf16* __restrict__ Ah,
                                           const bf16* __restrict__ Al,
                                           const bf16* __restrict__ Bh,
                                           const bf16* __restrict__ Bl,
                                           int K, int k0, int tid)
{
    // A tiles: 128 rows * 4 x 16B = 512 cp16 each -> 2 per thread
#pragma unroll
    for (int t = 0; t < 2; t++) {
        const char* G = (const char*)((t == 0 ? Ah : Al) + k0);
        uint32_t sbase = smem_u32(sm + (t == 0 ? OFF_AH : OFF_AL));
#pragma unroll
        for (int i = 0; i < 2; i++) {
            const int idx = tid + i * 256;
            const int row = idx >> 2, cc = idx & 3;
            cp16(sbase + row * ROWB + cc * 16, G + ((size_t)row * K + cc * 8) * 2);
        }
    }
    // B tiles: 256 rows * 4 x 16B = 1024 cp16 each -> 4 per thread
#pragma unroll
    for (int t = 0; t < 2; t++) {
        const char* G = (const char*)((t == 0 ? Bh : Bl) + k0);
        uint32_t sbase = smem_u32(sm + (t == 0 ? OFF_BH : OFF_BL));
#pragma unroll
        for (int i = 0; i < 4; i++) {
            const int idx = tid + i * 256;
            const int row = idx >> 2, cc = idx & 3;
            cp16(sbase + row * ROWB + cc * 16, G + ((size_t)row * K + cc * 8) * 2);
        }
    }
}

template<int EPI>
__global__ void __launch_bounds__(256, 1)
tgemm(const bf16* __restrict__ Ahi, const bf16* __restrict__ Alo,
      const bf16* __restrict__ Bhi, const bf16* __restrict__ Blo,
      int K, int N,
      float* __restrict__ Cf,
      bf16* __restrict__ Chi, bf16* __restrict__ Clo,
      const float* __restrict__ bias,
      const float* __restrict__ td,
      const float* __restrict__ ew)
{
    extern __shared__ char smem[];
    const int tid = threadIdx.x;
    const int w = tid >> 5, lid = tid & 31;
    const int wm = w & 1, wn = w >> 1;            // 2 x 4 warp grid
    const int m0 = blockIdx.y * 128;
    const int n0 = blockIdx.x * 256;

    const bf16* Ah = Ahi + (size_t)m0 * K;
    const bf16* Al = Alo + (size_t)m0 * K;
    const bf16* Bh = Bhi + (size_t)n0 * K;
    const bf16* Bl = Blo + (size_t)n0 * K;

    float acc[4][8][4];
#pragma unroll
    for (int i = 0; i < 4; i++)
#pragma unroll
        for (int j = 0; j < 8; j++)
#pragma unroll
            for (int k = 0; k < 4; k++) acc[i][j][k] = 0.f;

    const uint32_t sb = smem_u32(smem);
    const int NC = K >> 5;

    stage_load(smem, Ah, Al, Bh, Bl, K, 0, tid);
    CP_COMMIT();

    // per-thread ldmatrix address components (constant across iters)
    const uint32_t a_row = (uint32_t)(wm * 64 + (lid & 15)) * ROWB;
    const uint32_t a_kof = (uint32_t)(lid >> 4) * 16;
    const uint32_t b_row = (uint32_t)(wn * 64 + (lid & 7) + ((lid >> 4) * 8)) * ROWB;
    const uint32_t b_kof = (uint32_t)((lid >> 3) & 1) * 16;

    for (int c = 0; c < NC; c++) {
        if (c + 1 < NC)
            stage_load(smem + ((c + 1) & 1) * STAGE_SZ, Ah, Al, Bh, Bl, K, (c + 1) << 5, tid);
        CP_COMMIT();
        CP_WAIT1();
        __syncthreads();

        const uint32_t st = sb + (c & 1) * STAGE_SZ;
#pragma unroll
        for (int ks = 0; ks < 2; ks++) {
            uint32_t ah[4][4], al[4][4];
            const uint32_t ka = ks * 32 + a_kof;
#pragma unroll
            for (int mf = 0; mf < 4; mf++) {
                const uint32_t ra = st + a_row + (uint32_t)(mf * 16) * ROWB + ka;
                ldsm4(ah[mf], ra + OFF_AH);
                ldsm4(al[mf], ra + OFF_AL);
            }
            const uint32_t kb = ks * 32 + b_kof;
#pragma unroll
            for (int nf2 = 0; nf2 < 4; nf2++) {
                uint32_t bh[4], bl[4];
                const uint32_t rb = st + b_row + (uint32_t)(nf2 * 16) * ROWB + kb;
                ldsm4(bh, rb + OFF_BH);
                ldsm4(bl, rb + OFF_BL);
#pragma unroll
                for (int mf = 0; mf < 4; mf++) {
                    mma16816(acc[mf][nf2 * 2 + 0], ah[mf], bh + 0);
                    mma16816(acc[mf][nf2 * 2 + 0], ah[mf], bl + 0);
                    mma16816(acc[mf][nf2 * 2 + 0], al[mf], bh + 0);
                    mma16816(acc[mf][nf2 * 2 + 1], ah[mf], bh + 2);
                    mma16816(acc[mf][nf2 * 2 + 1], ah[mf], bl + 2);
                    mma16816(acc[mf][nf2 * 2 + 1], al[mf], bh + 2);
                }
            }
        }
        __syncthreads();
    }

    // ---- epilogue ----
    const int lrow = lid >> 2;
    const int lcol = (lid & 3) * 2;
    float sw = 0.f, esum = 0.f;
    if (EPI == 1) sw = 1.f / (1.f + expf(-ew[0]));

#pragma unroll
    for (int mf = 0; mf < 4; mf++) {
#pragma unroll
        for (int half = 0; half < 2; half++) {
            const int m = m0 + wm * 64 + mf * 16 + lrow + half * 8;
#pragma unroll
            for (int nf = 0; nf < 8; nf++) {
                const int n = n0 + wn * 64 + nf * 8 + lcol;
                float v0 = acc[mf][nf][half * 2 + 0];
                float v1 = acc[mf][nf][half * 2 + 1];

                if (EPI == 1) {
                    const float2 t2 = *(const float2*)(td + (size_t)m * N + n);
                    float e0 = fminf(1.f, fmaxf(-1.f, v0 - t2.x));
                    float e1 = fminf(1.f, fmaxf(-1.f, v1 - t2.y));
                    esum += e0 * e0 + e1 * e1;
                    v0 -= sw * e0;
                    v1 -= sw * e1;
                } else if (EPI == 2 || EPI == 3) {
                    const float2 b2 = *(const float2*)(bias + n);
                    v0 += b2.x; v1 += b2.y;
                    if (EPI == 2) {
                        v0 = 0.5f * v0 * (1.f + erff(v0 * 0.70710678118654752440f));
                        v1 = 0.5f * v1 * (1.f + erff(v1 * 0.70710678118654752440f));
                    }
                }

                if (EPI != 2)
                    *(float2*)(Cf + (size_t)m * N + n) = make_float2(v0, v1);
                if (EPI == 1 || EPI == 2) {
                    uint32_t lo;
                    const uint32_t hi = pksplit(v0, v1, lo);
                    *(uint32_t*)(Chi + (size_t)m * N + n) = hi;
                    *(uint32_t*)(Clo + (size_t)m * N + n) = lo;
                }
            }
        }
    }

    if (EPI == 1) {
#pragma unroll
        for (int o = 16; o > 0; o >>= 1) esum += __shfl_down_sync(0xffffffffu, esum, o);
        if (lid == 0) atomicAdd(&g_errsum, (double)esum);
    }
}

// ---------------------------------------------------------------------------
__global__ void finalize_pe(float* pe)
{
    float v = (float)(g_errsum * (1.0 / ((double)MR * (double)D_)));
    pe[0] = fminf(1.f, fmaxf(0.f, v));
}

// ---------------------------------------------------------------------------
extern "C" void kernel_launch(void* const* d_in, const int* in_sizes, int n_in,
                              void* d_out, int out_size)
{
    const float* bu        = (const float*)d_in[0];
    const float* td        = (const float*)d_in[1];
    const float* W_spec    = (const float*)d_in[2];
    const float* log_decay = (const float*)d_in[3];
    const float* freq      = (const float*)d_in[4];
    const float* W_from    = (const float*)d_in[5];
    const float* ln1_g     = (const float*)d_in[6];
    const float* ln1_b     = (const float*)d_in[7];
    const float* W1        = (const float*)d_in[8];
    const float* b1        = (const float*)d_in[9];
    const float* W2        = (const float*)d_in[10];
    const float* b2        = (const float*)d_in[11];
    const float* ln2_g     = (const float*)d_in[12];
    const float* ln2_b     = (const float*)d_in[13];
    const float* ew        = (const float*)d_in[14];

    static bool inited = false;
    static bf16 *xnh, *xnl, *soh, *sol, *coh, *col_, *hh, *hl;
    static bf16 *wsh, *wsl, *wfh, *wfl, *w1h, *w1l, *w2h, *w2l;
    static float *p_spec, *p_h2;
    if (!inited) {
        cudaGetSymbolAddress((void**)&xnh,  g_xn_hi);  cudaGetSymbolAddress((void**)&xnl,  g_xn_lo);
        cudaGetSymbolAddress((void**)&soh,  g_so_hi);  cudaGetSymbolAddress((void**)&sol,  g_so_lo);
        cudaGetSymbolAddress((void**)&coh,  g_co_hi);  cudaGetSymbolAddress((void**)&col_, g_co_lo);
        cudaGetSymbolAddress((void**)&hh,   g_h_hi);   cudaGetSymbolAddress((void**)&hl,   g_h_lo);
        cudaGetSymbolAddress((void**)&wsh,  g_ws_hi);  cudaGetSymbolAddress((void**)&wsl,  g_ws_lo);
        cudaGetSymbolAddress((void**)&wfh,  g_wf_hi);  cudaGetSymbolAddress((void**)&wfl,  g_wf_lo);
        cudaGetSymbolAddress((void**)&w1h,  g_w1_hi);  cudaGetSymbolAddress((void**)&w1l,  g_w1_lo);
        cudaGetSymbolAddress((void**)&w2h,  g_w2_hi);  cudaGetSymbolAddress((void**)&w2l,  g_w2_lo);
        cudaGetSymbolAddress((void**)&p_spec, g_spec);
        cudaGetSymbolAddress((void**)&p_h2,   g_h2);
        cudaFuncSetAttribute(tgemm<0>, cudaFuncAttributeMaxDynamicSharedMemorySize, SMEM_TOT);
        cudaFuncSetAttribute(tgemm<1>, cudaFuncAttributeMaxDynamicSharedMemorySize, SMEM_TOT);
        cudaFuncSetAttribute(tgemm<2>, cudaFuncAttributeMaxDynamicSharedMemorySize, SMEM_TOT);
        cudaFuncSetAttribute(tgemm<3>, cudaFuncAttributeMaxDynamicSharedMemorySize, SMEM_TOT);
        inited = true;
    }

    float* corrected = (float*)d_out;
    float* nextp     = corrected + (size_t)MR * D_;
    float* pe        = corrected + 2 * (size_t)MR * D_;

    // weight splits
    wsplit<<<(2 * F_ * D_) / 1024, 256>>>(W_spec, wsh, wsl, 2 * F_ * D_);
    wsplit<<<(D_ * 2 * F_) / 1024, 256>>>(W_from, wfh, wfl, D_ * 2 * F_);
    wsplit<<<(D_ * D_) / 1024, 256>>>(W1, w1h, w1l, D_ * D_);
    wsplit<<<(D_ * D_) / 1024, 256>>>(W2, w2h, w2l, D_ * D_);

    // 1) LN1 -> bf16 split
    ln_rows<1><<<MR, 256>>>(bu, ln1_g, ln1_b, nullptr, xnh, xnl);

    // 2) spectral = xn @ W_spec^T  [MR, 512] fp32
    tgemm<0><<<dim3((2 * F_) / 256, MR / 128), 256, SMEM_TOT>>>(
        xnh, xnl, wsh, wsl, D_, 2 * F_, p_spec, nullptr, nullptr,
        nullptr, nullptr, nullptr);

    // 3) causal complex scan (== FFT convolution)
    scan_carry <<<B_ * CCH, F_>>>(p_spec, log_decay, freq);
    scan_prefix<<<B_,       F_>>>(log_decay, freq);
    scan_final <<<B_ * CCH, F_>>>(p_spec, soh, sol, log_decay, freq);

    // 4) corrected = so @ W_from^T - sw*clip(...)   (+err^2)
    tgemm<1><<<dim3(D_ / 256, MR / 128), 256, SMEM_TOT>>>(
        soh, sol, wfh, wfl, 2 * F_, D_, corrected, coh, col_,
        nullptr, td, ew);

    // 5) h = gelu(corrected @ W1^T + b1) -> bf16 split
    tgemm<2><<<dim3(D_ / 256, MR / 128), 256, SMEM_TOT>>>(
        coh, col_, w1h, w1l, D_, D_, nullptr, hh, hl,
        b1, nullptr, nullptr);

    // 6) h2 = h @ W2^T + b2
    tgemm<3><<<dim3(D_ / 256, MR / 128), 256, SMEM_TOT>>>(
        hh, hl, w2h, w2l, D_, D_, p_h2, nullptr, nullptr,
        b2, nullptr, nullptr);

    // 7) next_prediction = LN2(h2)
    ln_rows<0><<<MR, 256>>>(p_h2, ln2_g, ln2_b, nextp, nullptr, nullptr);

    // 8) scalar
    finalize_pe<<<1, 1>>>(pe);
}

// round 16
// speedup vs baseline: 2.7683x; 1.3248x over previous
#include <cuda_runtime.h>
#include <cuda_fp16.h>
#include <math.h>
#include <stdint.h>

#define B_   4
#define S_   4096
#define D_   1024
#define F_   256
#define MR   (B_*S_)        // 16384 rows
#define CCH  64
#define LCH  (S_/CCH)

#define WSCALE     32.0f
#define INV_WSCALE 0.03125f

typedef __half h16;

// ---------------------------------------------------------------------------
// Device scratch (no allocations allowed)
// ---------------------------------------------------------------------------
__device__ h16    g_xn  [MR * D_];        // LN1 out (fp16)
__device__ float  g_spec[MR * 2 * F_];
__device__ h16    g_so  [MR * 2 * F_];    // scan out (fp16)
__device__ h16    g_co  [MR * D_];        // corrected (fp16 copy)
__device__ h16    g_h   [MR * D_];        // gelu out (fp16)
__device__ float  g_h2  [MR * D_];
__device__ h16    g_ws_hi[2 * F_ * D_];
__device__ h16    g_ws_lo[2 * F_ * D_];
__device__ h16    g_wf_hi[D_ * 2 * F_];
__device__ h16    g_wf_lo[D_ * 2 * F_];
__device__ h16    g_w1_hi[D_ * D_];
__device__ h16    g_w1_lo[D_ * D_];
__device__ h16    g_w2_hi[D_ * D_];
__device__ h16    g_w2_lo[D_ * D_];
__device__ float2 g_carry[B_ * CCH * F_];
__device__ float2 g_cin  [B_ * CCH * F_];
__device__ double g_errsum;

// ---------------------------------------------------------------------------
// PTX helpers (compute_103-safe: cp.async + ldmatrix + mma.sync only)
// ---------------------------------------------------------------------------
__device__ __forceinline__ uint32_t smem_u32(const void* p) {
    uint32_t a;
    asm("{ .reg .u64 t; cvta.to.shared.u64 t, %1; cvt.u32.u64 %0, t; }" : "=r"(a) : "l"(p));
    return a;
}
__device__ __forceinline__ void cp16(uint32_t sa, const void* ga) {
    asm volatile("cp.async.cg.shared.global [%0], [%1], 16;" :: "r"(sa), "l"(ga) : "memory");
}
#define CP_COMMIT() asm volatile("cp.async.commit_group;" ::: "memory")
#define CP_WAIT1()  asm volatile("cp.async.wait_group 1;" ::: "memory")

__device__ __forceinline__ void ldsm4(uint32_t* r, uint32_t a) {
    asm volatile("ldmatrix.sync.aligned.m8n8.x4.shared.b16 {%0,%1,%2,%3}, [%4];"
        : "=r"(r[0]), "=r"(r[1]), "=r"(r[2]), "=r"(r[3]) : "r"(a));
}
__device__ __forceinline__ void mma16816(float* c, const uint32_t* a, const uint32_t* b) {
    asm volatile("mma.sync.aligned.m16n8k16.row.col.f32.f16.f16.f32 "
        "{%0,%1,%2,%3}, {%4,%5,%6,%7}, {%8,%9}, {%0,%1,%2,%3};"
        : "+f"(c[0]), "+f"(c[1]), "+f"(c[2]), "+f"(c[3])
        : "r"(a[0]), "r"(a[1]), "r"(a[2]), "r"(a[3]), "r"(b[0]), "r"(b[1]));
}

__device__ __forceinline__ uint32_t pkh2(float a, float b) {
    __half2 h = __floats2half2_rn(a, b);
    return *(uint32_t*)&h;
}

// ---------------------------------------------------------------------------
// Weight split: fp32 -> scaled fp16 (hi, lo)
// ---------------------------------------------------------------------------
__global__ void wsplit(const float* __restrict__ w, h16* __restrict__ hi,
                       h16* __restrict__ lo, int n)
{
    const int i4 = (blockIdx.x * blockDim.x + threadIdx.x) * 4;
    if (i4 >= n) return;
    float4 v = *(const float4*)(w + i4);
    float s[4] = { v.x * WSCALE, v.y * WSCALE, v.z * WSCALE, v.w * WSCALE };
    h16 hh[4], ll[4];
#pragma unroll
    for (int j = 0; j < 4; j++) {
        hh[j] = __float2half_rn(s[j]);
        ll[j] = __float2half_rn(s[j] - __half2float(hh[j]));
    }
    *(uint2*)(hi + i4) = *(uint2*)hh;
    *(uint2*)(lo + i4) = *(uint2*)ll;
}

// ---------------------------------------------------------------------------
// LayerNorm (row of 1024, 256 threads). HALF=1: fp16 out, else fp32.
// ---------------------------------------------------------------------------
template<int HALF>
__global__ void ln_rows(const float* __restrict__ x, const float* __restrict__ g,
                        const float* __restrict__ bb, float* __restrict__ outf,
                        h16* __restrict__ oh)
{
    __shared__ float sh[16];
    const int row = blockIdx.x;
    const int t   = threadIdx.x;
    const float4* xr = (const float4*)(x + (size_t)row * D_);
    float4 v = xr[t];
    float s = v.x + v.y + v.z + v.w;
    float q = v.x*v.x + v.y*v.y + v.z*v.z + v.w*v.w;
#pragma unroll
    for (int o = 16; o > 0; o >>= 1) {
        s += __shfl_down_sync(0xffffffffu, s, o);
        q += __shfl_down_sync(0xffffffffu, q, o);
    }
    if ((t & 31) == 0) { sh[t >> 5] = s; sh[8 + (t >> 5)] = q; }
    __syncthreads();
    if (t == 0) {
        float S = 0.f, Q = 0.f;
#pragma unroll
        for (int w = 0; w < 8; w++) { S += sh[w]; Q += sh[8 + w]; }
        sh[0] = S; sh[8] = Q;
    }
    __syncthreads();
    const float mu  = sh[0] * (1.f / (float)D_);
    const float var = sh[8] * (1.f / (float)D_) - mu * mu;
    const float rs  = rsqrtf(var + 1e-5f);
    float4 gv = ((const float4*)g)[t];
    float4 bv = ((const float4*)bb)[t];
    float4 o;
    o.x = (v.x - mu) * rs * gv.x + bv.x;
    o.y = (v.y - mu) * rs * gv.y + bv.y;
    o.z = (v.z - mu) * rs * gv.z + bv.z;
    o.w = (v.w - mu) * rs * gv.w + bv.w;
    if (HALF) {
        ((uint2*)(oh + (size_t)row * D_))[t] =
            make_uint2(pkh2(o.x, o.y), pkh2(o.z, o.w));
    } else {
        ((float4*)(outf + (size_t)row * D_))[t] = o;
    }
}

// ---------------------------------------------------------------------------
// Spectral scan (== the FFT causal convolution)
// ---------------------------------------------------------------------------
__device__ __forceinline__ void get_Arot(const float* ld, const float* fr, int f,
                                         float& ar, float& ai, float& rr, float& ri)
{
    const float decay = 1.f / (1.f + expf(-ld[f]));
    const float om = tanhf(fr[f]) * 0.1f;
    rr = cosf(om); ri = sinf(om);
    ar = decay * rr; ai = decay * ri;
}

__global__ void scan_carry(const float* __restrict__ spec,
                           const float* __restrict__ ld, const float* __restrict__ fr)
{
    const int f = threadIdx.x;
    const int b = blockIdx.x / CCH;
    const int c = blockIdx.x % CCH;
    float ar, ai, rr, ri; get_Arot(ld, fr, f, ar, ai, rr, ri);
    float yr = 0.f, yi = 0.f;
    const float* base = spec + ((size_t)b * S_ + (size_t)c * LCH) * (2 * F_);
    for (int i = 0; i < LCH; i++) {
        const float ur = base[i * (2*F_) + f];
        const float ui = base[i * (2*F_) + F_ + f];
        const float br = rr*ur - ri*ui;
        const float bi = rr*ui + ri*ur;
        const float nr = ar*yr - ai*yi + br;
        const float ni = ar*yi + ai*yr + bi;
        yr = nr; yi = ni;
    }
    g_carry[((size_t)b * CCH + c) * F_ + f] = make_float2(yr, yi);
}

__global__ void scan_prefix(const float* __restrict__ ld, const float* __restrict__ fr)
{
    if (blockIdx.x == 0 && threadIdx.x == 0) g_errsum = 0.0;
    const int f = threadIdx.x;
    const int b = blockIdx.x;
    float ar, ai, rr, ri; get_Arot(ld, fr, f, ar, ai, rr, ri);
    float pr = ar, pi = ai;
#pragma unroll
    for (int j = 0; j < 6; j++) { float t = pr*pr - pi*pi; pi = 2.f*pr*pi; pr = t; }
    float sr = 0.f, si = 0.f;
    for (int c0 = 0; c0 < CCH; c0 += 8) {
        float2 cv[8];
#pragma unroll
        for (int j = 0; j < 8; j++)
            cv[j] = g_carry[((size_t)b * CCH + c0 + j) * F_ + f];
#pragma unroll
        for (int j = 0; j < 8; j++) {
            g_cin[((size_t)b * CCH + c0 + j) * F_ + f] = make_float2(sr, si);
            const float nr = pr*sr - pi*si + cv[j].x;
            const float ni = pr*si + pi*sr + cv[j].y;
            sr = nr; si = ni;
        }
    }
}

__global__ void scan_final(const float* __restrict__ spec,
                           h16* __restrict__ so,
                           const float* __restrict__ ld, const float* __restrict__ fr)
{
    const int f = threadIdx.x;
    const int b = blockIdx.x / CCH;
    const int c = blockIdx.x % CCH;
    float ar, ai, rr, ri; get_Arot(ld, fr, f, ar, ai, rr, ri);
    const float2 c0 = g_cin[((size_t)b * CCH + c) * F_ + f];
    float yr = c0.x, yi = c0.y;
    const size_t off = ((size_t)b * S_ + (size_t)c * LCH) * (2 * F_);
    const float* base = spec + off;
    for (int i = 0; i < LCH; i++) {
        const float ur = base[i * (2*F_) + f];
        const float ui = base[i * (2*F_) + F_ + f];
        const float br = rr*ur - ri*ui;
        const float bi = rr*ui + ri*ur;
        const float nr = ar*yr - ai*yi + br;
        const float ni = ar*yi + ai*yr + bi;
        yr = nr; yi = ni;
        const size_t pr_ = off + i * (2*F_) + f;
        so[pr_]      = __float2half_rn(yr);
        so[pr_ + F_] = __float2half_rn(yi);
    }
}

// ---------------------------------------------------------------------------
// mma.sync fp16 GEMM: C[M,N] = (1/32) * A16[M,K] * (Wh+Wl)[N,K]^T
// A single fp16, W split hi/lo fp16 (pre-scaled x32). 2 MMA products.
// CTA 128x256, 8 warps (2m x 4n), warp tile 64x64, K-chunk 32, cp.async x2.
// EPI: 0 = fp32 store; 1 = error/corrected (+err^2) fp32 + fp16 copy;
//      2 = bias+GELU fp16 out; 3 = bias fp32 out.
// ---------------------------------------------------------------------------
#define ROWB     80              // padded row stride (bytes)
#define A_TILE   (128 * ROWB)    // 10240
#define B_TILE   (256 * ROWB)    // 20480
#define OFF_A    0
#define OFF_BH   A_TILE
#define OFF_BL   (A_TILE + B_TILE)
#define STAGE_SZ (A_TILE + 2 * B_TILE)   // 51200
#define SMEM_TOT (2 * STAGE_SZ)          // 102400

__device__ __forceinline__ void stage_load(char* sm, const h16* __restrict__ A,
                                           const h16* __restrict__ Bh,
                                           const h16* __restrict__ Bl,
                                           int K, int k0, int tid)
{
    // A tile: 128 rows * 4 x 16B = 512 cp16 -> 2 per thread
    {
        const char* G = (const char*)(A + k0);
        uint32_t sbase = smem_u32(sm + OFF_A);
#pragma unroll
        for (int i = 0; i < 2; i++) {
            const int idx = tid + i * 256;
            const int row = idx >> 2, cc = idx & 3;
            cp16(sbase + row * ROWB + cc * 16, G + ((size_t)row * K + cc * 8) * 2);
        }
    }
    // B tiles: 256 rows * 4 x 16B = 1024 cp16 each -> 4 per thread
#pragma unroll
    for (int t = 0; t < 2; t++) {
        const char* G = (const char*)((t == 0 ? Bh : Bl) + k0);
        uint32_t sbase = smem_u32(sm + (t == 0 ? OFF_BH : OFF_BL));
#pragma unroll
        for (int i = 0; i < 4; i++) {
            const int idx = tid + i * 256;
            const int row = idx >> 2, cc = idx & 3;
            cp16(sbase + row * ROWB + cc * 16, G + ((size_t)row * K + cc * 8) * 2);
        }
    }
}

template<int EPI>
__global__ void __launch_bounds__(256, 1)
tgemm(const h16* __restrict__ Ain,
      const h16* __restrict__ Bhi, const h16* __restrict__ Blo,
      int K, int N,
      float* __restrict__ Cf, h16* __restrict__ Ch,
      const float* __restrict__ bias,
      const float* __restrict__ td,
      const float* __restrict__ ew)
{
    extern __shared__ char smem[];
    const int tid = threadIdx.x;
    const int w = tid >> 5, lid = tid & 31;
    const int wm = w & 1, wn = w >> 1;            // 2 x 4 warp grid
    const int m0 = blockIdx.y * 128;
    const int n0 = blockIdx.x * 256;

    const h16* A  = Ain + (size_t)m0 * K;
    const h16* Bh = Bhi + (size_t)n0 * K;
    const h16* Bl = Blo + (size_t)n0 * K;

    float acc[4][8][4];
#pragma unroll
    for (int i = 0; i < 4; i++)
#pragma unroll
        for (int j = 0; j < 8; j++)
#pragma unroll
            for (int k = 0; k < 4; k++) acc[i][j][k] = 0.f;

    const uint32_t sb = smem_u32(smem);
    const int NC = K >> 5;

    stage_load(smem, A, Bh, Bl, K, 0, tid);
    CP_COMMIT();

    const uint32_t a_row = (uint32_t)(wm * 64 + (lid & 15)) * ROWB;
    const uint32_t a_kof = (uint32_t)(lid >> 4) * 16;
    const uint32_t b_row = (uint32_t)(wn * 64 + (lid & 7) + ((lid >> 4) * 8)) * ROWB;
    const uint32_t b_kof = (uint32_t)((lid >> 3) & 1) * 16;

    for (int c = 0; c < NC; c++) {
        if (c + 1 < NC)
            stage_load(smem + ((c + 1) & 1) * STAGE_SZ, A, Bh, Bl, K, (c + 1) << 5, tid);
        CP_COMMIT();
        CP_WAIT1();
        __syncthreads();

        const uint32_t st = sb + (c & 1) * STAGE_SZ;
#pragma unroll
        for (int ks = 0; ks < 2; ks++) {
            uint32_t ah[4][4];
            const uint32_t ka = ks * 32 + a_kof;
#pragma unroll
            for (int mf = 0; mf < 4; mf++)
                ldsm4(ah[mf], st + a_row + (uint32_t)(mf * 16) * ROWB + ka + OFF_A);
            const uint32_t kb = ks * 32 + b_kof;
#pragma unroll
            for (int nf2 = 0; nf2 < 4; nf2++) {
                uint32_t bh[4], bl[4];
                const uint32_t rb = st + b_row + (uint32_t)(nf2 * 16) * ROWB + kb;
                ldsm4(bh, rb + OFF_BH);
                ldsm4(bl, rb + OFF_BL);
#pragma unroll
                for (int mf = 0; mf < 4; mf++) {
                    mma16816(acc[mf][nf2 * 2 + 0], ah[mf], bh + 0);
                    mma16816(acc[mf][nf2 * 2 + 0], ah[mf], bl + 0);
                    mma16816(acc[mf][nf2 * 2 + 1], ah[mf], bh + 2);
                    mma16816(acc[mf][nf2 * 2 + 1], ah[mf], bl + 2);
                }
            }
        }
        __syncthreads();
    }

    // ---- epilogue (unscale by 1/32, then fused op) ----
    const int lrow = lid >> 2;
    const int lcol = (lid & 3) * 2;
    float sw = 0.f, esum = 0.f;
    if (EPI == 1) sw = 1.f / (1.f + expf(-ew[0]));

#pragma unroll
    for (int mf = 0; mf < 4; mf++) {
#pragma unroll
        for (int half = 0; half < 2; half++) {
            const int m = m0 + wm * 64 + mf * 16 + lrow + half * 8;
#pragma unroll
            for (int nf = 0; nf < 8; nf++) {
                const int n = n0 + wn * 64 + nf * 8 + lcol;
                float v0 = acc[mf][nf][half * 2 + 0] * INV_WSCALE;
                float v1 = acc[mf][nf][half * 2 + 1] * INV_WSCALE;

                if (EPI == 1) {
                    const float2 t2 = *(const float2*)(td + (size_t)m * N + n);
                    float e0 = fminf(1.f, fmaxf(-1.f, v0 - t2.x));
                    float e1 = fminf(1.f, fmaxf(-1.f, v1 - t2.y));
                    esum += e0 * e0 + e1 * e1;
                    v0 -= sw * e0;
                    v1 -= sw * e1;
                } else if (EPI == 2 || EPI == 3) {
                    const float2 b2 = *(const float2*)(bias + n);
                    v0 += b2.x; v1 += b2.y;
                    if (EPI == 2) {
                        v0 = 0.5f * v0 * (1.f + erff(v0 * 0.70710678118654752440f));
                        v1 = 0.5f * v1 * (1.f + erff(v1 * 0.70710678118654752440f));
                    }
                }

                if (EPI != 2)
                    *(float2*)(Cf + (size_t)m * N + n) = make_float2(v0, v1);
                if (EPI == 1 || EPI == 2)
                    *(uint32_t*)(Ch + (size_t)m * N + n) = pkh2(v0, v1);
            }
        }
    }

    if (EPI == 1) {
#pragma unroll
        for (int o = 16; o > 0; o >>= 1) esum += __shfl_down_sync(0xffffffffu, esum, o);
        if (lid == 0) atomicAdd(&g_errsum, (double)esum);
    }
}

// ---------------------------------------------------------------------------
__global__ void finalize_pe(float* pe)
{
    float v = (float)(g_errsum * (1.0 / ((double)MR * (double)D_)));
    pe[0] = fminf(1.f, fmaxf(0.f, v));
}

// ---------------------------------------------------------------------------
extern "C" void kernel_launch(void* const* d_in, const int* in_sizes, int n_in,
                              void* d_out, int out_size)
{
    const float* bu        = (const float*)d_in[0];
    const float* td        = (const float*)d_in[1];
    const float* W_spec    = (const float*)d_in[2];
    const float* log_decay = (const float*)d_in[3];
    const float* freq      = (const float*)d_in[4];
    const float* W_from    = (const float*)d_in[5];
    const float* ln1_g     = (const float*)d_in[6];
    const float* ln1_b     = (const float*)d_in[7];
    const float* W1        = (const float*)d_in[8];
    const float* b1        = (const float*)d_in[9];
    const float* W2        = (const float*)d_in[10];
    const float* b2        = (const float*)d_in[11];
    const float* ln2_g     = (const float*)d_in[12];
    const float* ln2_b     = (const float*)d_in[13];
    const float* ew        = (const float*)d_in[14];

    static bool inited = false;
    static h16 *xn, *so, *co, *hq;
    static h16 *wsh, *wsl, *wfh, *wfl, *w1h, *w1l, *w2h, *w2l;
    static float *p_spec, *p_h2;
    if (!inited) {
        cudaGetSymbolAddress((void**)&xn,  g_xn);
        cudaGetSymbolAddress((void**)&so,  g_so);
        cudaGetSymbolAddress((void**)&co,  g_co);
        cudaGetSymbolAddress((void**)&hq,  g_h);
        cudaGetSymbolAddress((void**)&wsh, g_ws_hi); cudaGetSymbolAddress((void**)&wsl, g_ws_lo);
        cudaGetSymbolAddress((void**)&wfh, g_wf_hi); cudaGetSymbolAddress((void**)&wfl, g_wf_lo);
        cudaGetSymbolAddress((void**)&w1h, g_w1_hi); cudaGetSymbolAddress((void**)&w1l, g_w1_lo);
        cudaGetSymbolAddress((void**)&w2h, g_w2_hi); cudaGetSymbolAddress((void**)&w2l, g_w2_lo);
        cudaGetSymbolAddress((void**)&p_spec, g_spec);
        cudaGetSymbolAddress((void**)&p_h2,   g_h2);
        cudaFuncSetAttribute(tgemm<0>, cudaFuncAttributeMaxDynamicSharedMemorySize, SMEM_TOT);
        cudaFuncSetAttribute(tgemm<1>, cudaFuncAttributeMaxDynamicSharedMemorySize, SMEM_TOT);
        cudaFuncSetAttribute(tgemm<2>, cudaFuncAttributeMaxDynamicSharedMemorySize, SMEM_TOT);
        cudaFuncSetAttribute(tgemm<3>, cudaFuncAttributeMaxDynamicSharedMemorySize, SMEM_TOT);
        inited = true;
    }

    float* corrected = (float*)d_out;
    float* nextp     = corrected + (size_t)MR * D_;
    float* pe        = corrected + 2 * (size_t)MR * D_;

    // weight splits (scaled x32)
    wsplit<<<(2 * F_ * D_) / 1024, 256>>>(W_spec, wsh, wsl, 2 * F_ * D_);
    wsplit<<<(D_ * 2 * F_) / 1024, 256>>>(W_from, wfh, wfl, D_ * 2 * F_);
    wsplit<<<(D_ * D_) / 1024, 256>>>(W1, w1h, w1l, D_ * D_);
    wsplit<<<(D_ * D_) / 1024, 256>>>(W2, w2h, w2l, D_ * D_);

    // 1) LN1 -> fp16
    ln_rows<1><<<MR, 256>>>(bu, ln1_g, ln1_b, nullptr, xn);

    // 2) spectral = xn @ W_spec^T  [MR, 512] fp32
    tgemm<0><<<dim3((2 * F_) / 256, MR / 128), 256, SMEM_TOT>>>(
        xn, wsh, wsl, D_, 2 * F_, p_spec, nullptr, nullptr, nullptr, nullptr);

    // 3) causal complex scan (== FFT convolution)
    scan_carry <<<B_ * CCH, F_>>>(p_spec, log_decay, freq);
    scan_prefix<<<B_,       F_>>>(log_decay, freq);
    scan_final <<<B_ * CCH, F_>>>(p_spec, so, log_decay, freq);

    // 4) corrected = so @ W_from^T - sw*clip(...)   (+err^2)
    tgemm<1><<<dim3(D_ / 256, MR / 128), 256, SMEM_TOT>>>(
        so, wfh, wfl, 2 * F_, D_, corrected, co, nullptr, td, ew);

    // 5) h = gelu(corrected @ W1^T + b1) -> fp16
    tgemm<2><<<dim3(D_ / 256, MR / 128), 256, SMEM_TOT>>>(
        co, w1h, w1l, D_, D_, nullptr, hq, b1, nullptr, nullptr);

    // 6) h2 = h @ W2^T + b2
    tgemm<3><<<dim3(D_ / 256, MR / 128), 256, SMEM_TOT>>>(
        hq, w2h, w2l, D_, D_, p_h2, nullptr, b2, nullptr, nullptr);

    // 7) next_prediction = LN2(h2)
    ln_rows<0><<<MR, 256>>>(p_h2, ln2_g, ln2_b, nextp, nullptr);

    // 8) scalar
    finalize_pe<<<1, 1>>>(pe);
}

// round 17
// speedup vs baseline: 4.2390x; 1.5313x over previous
#include <cuda_runtime.h>
#include <cuda_fp16.h>
#include <math.h>
#include <stdint.h>

#define B_   4
#define S_   4096
#define D_   1024
#define F_   256
#define MR   (B_*S_)        // 16384 rows
#define CCH  64
#define LCH  (S_/CCH)

#define WSCALE     32.0f
#define INV_WSCALE 0.03125f

typedef __half h16;

// ---------------------------------------------------------------------------
// Device scratch (no allocations allowed)
// ---------------------------------------------------------------------------
__device__ h16    g_xn  [MR * D_];        // LN1 out (fp16)
__device__ float  g_spec[MR * 2 * F_];
__device__ h16    g_so  [MR * 2 * F_];    // scan out (fp16)
__device__ h16    g_co  [MR * D_];        // corrected (fp16 copy)
__device__ h16    g_h   [MR * D_];        // gelu out (fp16)
__device__ float  g_h2  [MR * D_];
__device__ h16    g_ws  [2 * F_ * D_];    // fp16 weights (scaled x32)
__device__ h16    g_wf  [D_ * 2 * F_];
__device__ h16    g_w1  [D_ * D_];
__device__ h16    g_w2  [D_ * D_];
__device__ float2 g_carry[B_ * CCH * F_];
__device__ float2 g_cin  [B_ * CCH * F_];
__device__ double g_errsum;

// ---------------------------------------------------------------------------
// PTX helpers (compute_103-safe: cp.async + ldmatrix + mma.sync only)
// ---------------------------------------------------------------------------
__device__ __forceinline__ uint32_t smem_u32(const void* p) {
    uint32_t a;
    asm("{ .reg .u64 t; cvta.to.shared.u64 t, %1; cvt.u32.u64 %0, t; }" : "=r"(a) : "l"(p));
    return a;
}
__device__ __forceinline__ void cp16(uint32_t sa, const void* ga) {
    asm volatile("cp.async.cg.shared.global [%0], [%1], 16;" :: "r"(sa), "l"(ga) : "memory");
}
#define CP_COMMIT() asm volatile("cp.async.commit_group;" ::: "memory")
#define CP_WAIT1()  asm volatile("cp.async.wait_group 1;" ::: "memory")

__device__ __forceinline__ void ldsm4(uint32_t* r, uint32_t a) {
    asm volatile("ldmatrix.sync.aligned.m8n8.x4.shared.b16 {%0,%1,%2,%3}, [%4];"
        : "=r"(r[0]), "=r"(r[1]), "=r"(r[2]), "=r"(r[3]) : "r"(a));
}
__device__ __forceinline__ void mma16816(float* c, const uint32_t* a, const uint32_t* b) {
    asm volatile("mma.sync.aligned.m16n8k16.row.col.f32.f16.f16.f32 "
        "{%0,%1,%2,%3}, {%4,%5,%6,%7}, {%8,%9}, {%0,%1,%2,%3};"
        : "+f"(c[0]), "+f"(c[1]), "+f"(c[2]), "+f"(c[3])
        : "r"(a[0]), "r"(a[1]), "r"(a[2]), "r"(a[3]), "r"(b[0]), "r"(b[1]));
}

__device__ __forceinline__ uint32_t pkh2(float a, float b) {
    __half2 h = __floats2half2_rn(a, b);
    return *(uint32_t*)&h;
}

// ---------------------------------------------------------------------------
// Weight convert: fp32 -> fp16 (scaled x32)
// ---------------------------------------------------------------------------
__global__ void wconv(const float* __restrict__ w, h16* __restrict__ o, int n)
{
    const int i4 = (blockIdx.x * blockDim.x + threadIdx.x) * 4;
    if (i4 >= n) return;
    float4 v = *(const float4*)(w + i4);
    *(uint2*)(o + i4) = make_uint2(pkh2(v.x * WSCALE, v.y * WSCALE),
                                   pkh2(v.z * WSCALE, v.w * WSCALE));
}

// ---------------------------------------------------------------------------
// LayerNorm (row of 1024, 256 threads). HALF=1: fp16 out, else fp32.
// ---------------------------------------------------------------------------
template<int HALF>
__global__ void ln_rows(const float* __restrict__ x, const float* __restrict__ g,
                        const float* __restrict__ bb, float* __restrict__ outf,
                        h16* __restrict__ oh)
{
    __shared__ float sh[16];
    const int row = blockIdx.x;
    const int t   = threadIdx.x;
    const float4* xr = (const float4*)(x + (size_t)row * D_);
    float4 v = xr[t];
    float s = v.x + v.y + v.z + v.w;
    float q = v.x*v.x + v.y*v.y + v.z*v.z + v.w*v.w;
#pragma unroll
    for (int o = 16; o > 0; o >>= 1) {
        s += __shfl_down_sync(0xffffffffu, s, o);
        q += __shfl_down_sync(0xffffffffu, q, o);
    }
    if ((t & 31) == 0) { sh[t >> 5] = s; sh[8 + (t >> 5)] = q; }
    __syncthreads();
    if (t == 0) {
        float S = 0.f, Q = 0.f;
#pragma unroll
        for (int w = 0; w < 8; w++) { S += sh[w]; Q += sh[8 + w]; }
        sh[0] = S; sh[8] = Q;
    }
    __syncthreads();
    const float mu  = sh[0] * (1.f / (float)D_);
    const float var = sh[8] * (1.f / (float)D_) - mu * mu;
    const float rs  = rsqrtf(var + 1e-5f);
    float4 gv = ((const float4*)g)[t];
    float4 bv = ((const float4*)bb)[t];
    float4 o;
    o.x = (v.x - mu) * rs * gv.x + bv.x;
    o.y = (v.y - mu) * rs * gv.y + bv.y;
    o.z = (v.z - mu) * rs * gv.z + bv.z;
    o.w = (v.w - mu) * rs * gv.w + bv.w;
    if (HALF) {
        ((uint2*)(oh + (size_t)row * D_))[t] =
            make_uint2(pkh2(o.x, o.y), pkh2(o.z, o.w));
    } else {
        ((float4*)(outf + (size_t)row * D_))[t] = o;
    }
}

// ---------------------------------------------------------------------------
// Spectral scan (== the FFT causal convolution)
// ---------------------------------------------------------------------------
__device__ __forceinline__ void get_Arot(const float* ld, const float* fr, int f,
                                         float& ar, float& ai, float& rr, float& ri)
{
    const float decay = 1.f / (1.f + expf(-ld[f]));
    const float om = tanhf(fr[f]) * 0.1f;
    rr = cosf(om); ri = sinf(om);
    ar = decay * rr; ai = decay * ri;
}

__global__ void scan_carry(const float* __restrict__ spec,
                           const float* __restrict__ ld, const float* __restrict__ fr)
{
    const int f = threadIdx.x;
    const int b = blockIdx.x / CCH;
    const int c = blockIdx.x % CCH;
    float ar, ai, rr, ri; get_Arot(ld, fr, f, ar, ai, rr, ri);
    float yr = 0.f, yi = 0.f;
    const float* base = spec + ((size_t)b * S_ + (size_t)c * LCH) * (2 * F_);
    for (int i = 0; i < LCH; i++) {
        const float ur = base[i * (2*F_) + f];
        const float ui = base[i * (2*F_) + F_ + f];
        const float br = rr*ur - ri*ui;
        const float bi = rr*ui + ri*ur;
        const float nr = ar*yr - ai*yi + br;
        const float ni = ar*yi + ai*yr + bi;
        yr = nr; yi = ni;
    }
    g_carry[((size_t)b * CCH + c) * F_ + f] = make_float2(yr, yi);
}

__global__ void scan_prefix(const float* __restrict__ ld, const float* __restrict__ fr)
{
    if (blockIdx.x == 0 && threadIdx.x == 0) g_errsum = 0.0;
    const int f = threadIdx.x;
    const int b = blockIdx.x;
    float ar, ai, rr, ri; get_Arot(ld, fr, f, ar, ai, rr, ri);
    float pr = ar, pi = ai;
#pragma unroll
    for (int j = 0; j < 6; j++) { float t = pr*pr - pi*pi; pi = 2.f*pr*pi; pr = t; }
    float sr = 0.f, si = 0.f;
    for (int c0 = 0; c0 < CCH; c0 += 8) {
        float2 cv[8];
#pragma unroll
        for (int j = 0; j < 8; j++)
            cv[j] = g_carry[((size_t)b * CCH + c0 + j) * F_ + f];
#pragma unroll
        for (int j = 0; j < 8; j++) {
            g_cin[((size_t)b * CCH + c0 + j) * F_ + f] = make_float2(sr, si);
            const float nr = pr*sr - pi*si + cv[j].x;
            const float ni = pr*si + pi*sr + cv[j].y;
            sr = nr; si = ni;
        }
    }
}

__global__ void scan_final(const float* __restrict__ spec,
                           h16* __restrict__ so,
                           const float* __restrict__ ld, const float* __restrict__ fr)
{
    const int f = threadIdx.x;
    const int b = blockIdx.x / CCH;
    const int c = blockIdx.x % CCH;
    float ar, ai, rr, ri; get_Arot(ld, fr, f, ar, ai, rr, ri);
    const float2 c0 = g_cin[((size_t)b * CCH + c) * F_ + f];
    float yr = c0.x, yi = c0.y;
    const size_t off = ((size_t)b * S_ + (size_t)c * LCH) * (2 * F_);
    const float* base = spec + off;
    for (int i = 0; i < LCH; i++) {
        const float ur = base[i * (2*F_) + f];
        const float ui = base[i * (2*F_) + F_ + f];
        const float br = rr*ur - ri*ui;
        const float bi = rr*ui + ri*ur;
        const float nr = ar*yr - ai*yi + br;
        const float ni = ar*yi + ai*yr + bi;
        yr = nr; yi = ni;
        const size_t pr_ = off + i * (2*F_) + f;
        so[pr_]      = __float2half_rn(yr);
        so[pr_ + F_] = __float2half_rn(yi);
    }
}

// ---------------------------------------------------------------------------
// mma.sync fp16 GEMM: C[M,N] = (1/32) * A16[M,K] * W16[N,K]^T
// Single product (fp16 activations x fp16 scaled weights).
// CTA 128x256, 8 warps (2m x 4n), warp tile 64x64, K-chunk 32, cp.async x2.
// EPI: 0 = fp32 store; 1 = error/corrected (+err^2) fp32 + fp16 copy;
//      2 = bias+GELU fp16 out; 3 = bias fp32 out.
// ---------------------------------------------------------------------------
#define ROWB     80              // padded row stride (bytes)
#define A_TILE   (128 * ROWB)    // 10240
#define B_TILE   (256 * ROWB)    // 20480
#define OFF_A    0
#define OFF_B    A_TILE
#define STAGE_SZ (A_TILE + B_TILE)       // 30720
#define SMEM_TOT (2 * STAGE_SZ)          // 61440

__device__ __forceinline__ void stage_load(char* sm, const h16* __restrict__ A,
                                           const h16* __restrict__ Bw,
                                           int K, int k0, int tid)
{
    // A tile: 128 rows * 4 x 16B = 512 cp16 -> 2 per thread
    {
        const char* G = (const char*)(A + k0);
        uint32_t sbase = smem_u32(sm + OFF_A);
#pragma unroll
        for (int i = 0; i < 2; i++) {
            const int idx = tid + i * 256;
            const int row = idx >> 2, cc = idx & 3;
            cp16(sbase + row * ROWB + cc * 16, G + ((size_t)row * K + cc * 8) * 2);
        }
    }
    // B tile: 256 rows * 4 x 16B = 1024 cp16 -> 4 per thread
    {
        const char* G = (const char*)(Bw + k0);
        uint32_t sbase = smem_u32(sm + OFF_B);
#pragma unroll
        for (int i = 0; i < 4; i++) {
            const int idx = tid + i * 256;
            const int row = idx >> 2, cc = idx & 3;
            cp16(sbase + row * ROWB + cc * 16, G + ((size_t)row * K + cc * 8) * 2);
        }
    }
}

template<int EPI>
__global__ void __launch_bounds__(256, 1)
tgemm(const h16* __restrict__ Ain, const h16* __restrict__ Bin,
      int K, int N,
      float* __restrict__ Cf, h16* __restrict__ Ch,
      const float* __restrict__ bias,
      const float* __restrict__ td,
      const float* __restrict__ ew)
{
    extern __shared__ char smem[];
    const int tid = threadIdx.x;
    const int w = tid >> 5, lid = tid & 31;
    const int wm = w & 1, wn = w >> 1;            // 2 x 4 warp grid
    const int m0 = blockIdx.y * 128;
    const int n0 = blockIdx.x * 256;

    const h16* A  = Ain + (size_t)m0 * K;
    const h16* Bw = Bin + (size_t)n0 * K;

    float acc[4][8][4];
#pragma unroll
    for (int i = 0; i < 4; i++)
#pragma unroll
        for (int j = 0; j < 8; j++)
#pragma unroll
            for (int k = 0; k < 4; k++) acc[i][j][k] = 0.f;

    const uint32_t sb = smem_u32(smem);
    const int NC = K >> 5;

    stage_load(smem, A, Bw, K, 0, tid);
    CP_COMMIT();

    const uint32_t a_row = (uint32_t)(wm * 64 + (lid & 15)) * ROWB;
    const uint32_t a_kof = (uint32_t)(lid >> 4) * 16;
    const uint32_t b_row = (uint32_t)(wn * 64 + (lid & 7) + ((lid >> 4) * 8)) * ROWB;
    const uint32_t b_kof = (uint32_t)((lid >> 3) & 1) * 16;

    for (int c = 0; c < NC; c++) {
        if (c + 1 < NC)
            stage_load(smem + ((c + 1) & 1) * STAGE_SZ, A, Bw, K, (c + 1) << 5, tid);
        CP_COMMIT();
        CP_WAIT1();
        __syncthreads();

        const uint32_t st = sb + (c & 1) * STAGE_SZ;
#pragma unroll
        for (int ks = 0; ks < 2; ks++) {
            uint32_t ah[4][4];
            const uint32_t ka = ks * 32 + a_kof;
#pragma unroll
            for (int mf = 0; mf < 4; mf++)
                ldsm4(ah[mf], st + a_row + (uint32_t)(mf * 16) * ROWB + ka + OFF_A);
            const uint32_t kb = ks * 32 + b_kof;
#pragma unroll
            for (int nf2 = 0; nf2 < 4; nf2++) {
                uint32_t bh[4];
                ldsm4(bh, st + b_row + (uint32_t)(nf2 * 16) * ROWB + kb + OFF_B);
#pragma unroll
                for (int mf = 0; mf < 4; mf++) {
                    mma16816(acc[mf][nf2 * 2 + 0], ah[mf], bh + 0);
                    mma16816(acc[mf][nf2 * 2 + 1], ah[mf], bh + 2);
                }
            }
        }
        __syncthreads();
    }

    // ---- epilogue (unscale by 1/32, then fused op) ----
    const int lrow = lid >> 2;
    const int lcol = (lid & 3) * 2;
    float sw = 0.f, esum = 0.f;
    if (EPI == 1) sw = 1.f / (1.f + expf(-ew[0]));

#pragma unroll
    for (int mf = 0; mf < 4; mf++) {
#pragma unroll
        for (int half = 0; half < 2; half++) {
            const int m = m0 + wm * 64 + mf * 16 + lrow + half * 8;
#pragma unroll
            for (int nf = 0; nf < 8; nf++) {
                const int n = n0 + wn * 64 + nf * 8 + lcol;
                float v0 = acc[mf][nf][half * 2 + 0] * INV_WSCALE;
                float v1 = acc[mf][nf][half * 2 + 1] * INV_WSCALE;

                if (EPI == 1) {
                    const float2 t2 = *(const float2*)(td + (size_t)m * N + n);
                    float e0 = fminf(1.f, fmaxf(-1.f, v0 - t2.x));
                    float e1 = fminf(1.f, fmaxf(-1.f, v1 - t2.y));
                    esum += e0 * e0 + e1 * e1;
                    v0 -= sw * e0;
                    v1 -= sw * e1;
                } else if (EPI == 2 || EPI == 3) {
                    const float2 b2 = *(const float2*)(bias + n);
                    v0 += b2.x; v1 += b2.y;
                    if (EPI == 2) {
                        v0 = 0.5f * v0 * (1.f + erff(v0 * 0.70710678118654752440f));
                        v1 = 0.5f * v1 * (1.f + erff(v1 * 0.70710678118654752440f));
                    }
                }

                if (EPI != 2)
                    *(float2*)(Cf + (size_t)m * N + n) = make_float2(v0, v1);
                if (EPI == 1 || EPI == 2)
                    *(uint32_t*)(Ch + (size_t)m * N + n) = pkh2(v0, v1);
            }
        }
    }

    if (EPI == 1) {
#pragma unroll
        for (int o = 16; o > 0; o >>= 1) esum += __shfl_down_sync(0xffffffffu, esum, o);
        if (lid == 0) atomicAdd(&g_errsum, (double)esum);
    }
}

// ---------------------------------------------------------------------------
__global__ void finalize_pe(float* pe)
{
    float v = (float)(g_errsum * (1.0 / ((double)MR * (double)D_)));
    pe[0] = fminf(1.f, fmaxf(0.f, v));
}

// ---------------------------------------------------------------------------
extern "C" void kernel_launch(void* const* d_in, const int* in_sizes, int n_in,
                              void* d_out, int out_size)
{
    const float* bu        = (const float*)d_in[0];
    const float* td        = (const float*)d_in[1];
    const float* W_spec    = (const float*)d_in[2];
    const float* log_decay = (const float*)d_in[3];
    const float* freq      = (const float*)d_in[4];
    const float* W_from    = (const float*)d_in[5];
    const float* ln1_g     = (const float*)d_in[6];
    const float* ln1_b     = (const float*)d_in[7];
    const float* W1        = (const float*)d_in[8];
    const float* b1        = (const float*)d_in[9];
    const float* W2        = (const float*)d_in[10];
    const float* b2        = (const float*)d_in[11];
    const float* ln2_g     = (const float*)d_in[12];
    const float* ln2_b     = (const float*)d_in[13];
    const float* ew        = (const float*)d_in[14];

    static bool inited = false;
    static h16 *xn, *so, *co, *hq;
    static h16 *ws, *wf, *w1, *w2;
    static float *p_spec, *p_h2;
    if (!inited) {
        cudaGetSymbolAddress((void**)&xn,  g_xn);
        cudaGetSymbolAddress((void**)&so,  g_so);
        cudaGetSymbolAddress((void**)&co,  g_co);
        cudaGetSymbolAddress((void**)&hq,  g_h);
        cudaGetSymbolAddress((void**)&ws,  g_ws);
        cudaGetSymbolAddress((void**)&wf,  g_wf);
        cudaGetSymbolAddress((void**)&w1,  g_w1);
        cudaGetSymbolAddress((void**)&w2,  g_w2);
        cudaGetSymbolAddress((void**)&p_spec, g_spec);
        cudaGetSymbolAddress((void**)&p_h2,   g_h2);
        cudaFuncSetAttribute(tgemm<0>, cudaFuncAttributeMaxDynamicSharedMemorySize, SMEM_TOT);
        cudaFuncSetAttribute(tgemm<1>, cudaFuncAttributeMaxDynamicSharedMemorySize, SMEM_TOT);
        cudaFuncSetAttribute(tgemm<2>, cudaFuncAttributeMaxDynamicSharedMemorySize, SMEM_TOT);
        cudaFuncSetAttribute(tgemm<3>, cudaFuncAttributeMaxDynamicSharedMemorySize, SMEM_TOT);
        inited = true;
    }

    float* corrected = (float*)d_out;
    float* nextp     = corrected + (size_t)MR * D_;
    float* pe        = corrected + 2 * (size_t)MR * D_;

    // weight converts (scaled x32)
    wconv<<<(2 * F_ * D_) / 1024, 256>>>(W_spec, ws, 2 * F_ * D_);
    wconv<<<(D_ * 2 * F_) / 1024, 256>>>(W_from, wf, D_ * 2 * F_);
    wconv<<<(D_ * D_) / 1024, 256>>>(W1, w1, D_ * D_);
    wconv<<<(D_ * D_) / 1024, 256>>>(W2, w2, D_ * D_);

    // 1) LN1 -> fp16
    ln_rows<1><<<MR, 256>>>(bu, ln1_g, ln1_b, nullptr, xn);

    // 2) spectral = xn @ W_spec^T  [MR, 512] fp32
    tgemm<0><<<dim3((2 * F_) / 256, MR / 128), 256, SMEM_TOT>>>(
        xn, ws, D_, 2 * F_, p_spec, nullptr, nullptr, nullptr, nullptr);

    // 3) causal complex scan (== FFT convolution)
    scan_carry <<<B_ * CCH, F_>>>(p_spec, log_decay, freq);
    scan_prefix<<<B_,       F_>>>(log_decay, freq);
    scan_final <<<B_ * CCH, F_>>>(p_spec, so, log_decay, freq);

    // 4) corrected = so @ W_from^T - sw*clip(...)   (+err^2)
    tgemm<1><<<dim3(D_ / 256, MR / 128), 256, SMEM_TOT>>>(
        so, wf, 2 * F_, D_, corrected, co, nullptr, td, ew);

    // 5) h = gelu(corrected @ W1^T + b1) -> fp16
    tgemm<2><<<dim3(D_ / 256, MR / 128), 256, SMEM_TOT>>>(
        co, w1, D_, D_, nullptr, hq, b1, nullptr, nullptr);

    // 6) h2 = h @ W2^T + b2
    tgemm<3><<<dim3(D_ / 256, MR / 128), 256, SMEM_TOT>>>(
        hq, w2, D_, D_, p_h2, nullptr, b2, nullptr, nullptr);

    // 7) next_prediction = LN2(h2)
    ln_rows<0><<<MR, 256>>>(p_h2, ln2_g, ln2_b, nextp, nullptr);

    // 8) scalar
    finalize_pe<<<1, 1>>>(pe);
}